// round 1
// baseline (speedup 1.0000x reference)
#include <cuda_runtime.h>
#include <cstdint>
#include <cstddef>

#define BATCH 8
#define CH 64
#define HH 256
#define WW 256
#define MM 12
#define KXM 24
#define NLAYERS 4
#define FCH 128
#define HW (HH*WW)
#define BCHW (BATCH*CH*HW)

// ---------------- device scratch (no runtime allocation allowed) ----------------
__device__ float g_h[2][BCHW];                 // ping-pong activations [b,c,x,y]
__device__ float g_Fy[BATCH*CH*HH*MM*2];       // [b,c,x,ky,(re,im)]
__device__ float g_G [BATCH*CH*KXM*MM*2];      // [b,c, j*12+ky, (re,im)]
__device__ float g_G2[BATCH*CH*KXM*MM*2];      // [b,o, j*12+ky, (re,im)]
__device__ float g_E [BATCH*CH*HH*MM*2];       // [b,o,x, ky,(re,im)]  (x-inverse done, /65536)
__device__ float g_TY[HH*MM*2];                // forward y basis: cos,sin(2pi ky y/256)
__device__ float g_TX[KXM*HH*2];               // x twiddles: cos,sin(2pi kx_eff x/256)
__device__ float g_TYinv[KXM*HH];              // inverse-y real basis rows [k][y]

__device__ __forceinline__ float gelu_f(float v){
    return 0.5f*v*(1.0f + erff(v*0.70710678118654752f));
}

// ---------------- twiddle tables (cheap, rebuilt every launch) ----------------
__global__ void k_tables(){
    int t = blockIdx.x*blockDim.x + threadIdx.x;
    if (t < HH*MM){
        int y = t/MM, ky = t%MM;
        int r = (ky*y) & 255;
        double s,c; sincospi(2.0*r/256.0, &s, &c);
        g_TY[2*t]   = (float)c;
        g_TY[2*t+1] = (float)s;
    }
    if (t < KXM*HH){
        {
            int j = t/HH, xx = t%HH;
            int k = (j<12)? j : (j-24);          // kx 244..255 == -12..-1
            int r = ((k*xx)%256 + 256) & 255;
            double s,c; sincospi(2.0*r/256.0, &s, &c);
            g_TX[2*t]   = (float)c;
            g_TX[2*t+1] = (float)s;
        }
        {
            int kk = t/HH, y = t%HH;
            int ky2 = kk>>1;
            int r2 = (ky2*y) & 255;
            double s2,c2; sincospi(2.0*r2/256.0, &s2, &c2);
            float v;
            if ((kk&1)==0) v = (ky2==0)? 1.0f : 2.0f*(float)c2;
            else           v = (ky2==0)? 0.0f : -2.0f*(float)s2;
            g_TYinv[t] = v;
        }
    }
}

// ---------------- lift: h0 = fc0([x, gx, gy]) ----------------
__global__ void k_lift(const float* __restrict__ x, const float* __restrict__ fw,
                       const float* __restrict__ fb){
    __shared__ float w[CH*3];
    __shared__ float bsh[CH];
    if (threadIdx.x < CH*3) w[threadIdx.x]   = fw[threadIdx.x];
    if (threadIdx.x < CH)   bsh[threadIdx.x] = fb[threadIdx.x];
    __syncthreads();
    int b = blockIdx.x>>8, xr = blockIdx.x&255;
    int y = threadIdx.x;
    float xin = x[(((size_t)b)<<16) + (xr<<8) + y];
    float gx = xr*(1.0f/255.0f), gy = y*(1.0f/255.0f);
    for (int wo=0; wo<CH; wo++){
        float v = w[wo*3]*xin + w[wo*3+1]*gx + w[wo*3+2]*gy + bsh[wo];
        g_h[0][(((size_t)(b*CH+wo))<<16) + (xr<<8) + y] = v;
    }
}

// ---------------- K1: DFT over y, 12 modes (one thread per (b,c,x) row) ----------------
__global__ void k_dfty(int src){
    __shared__ float ty[HH*MM*2];
    for (int i=threadIdx.x; i<HH*MM*2; i+=blockDim.x) ty[i]=g_TY[i];
    __syncthreads();
    int row = blockIdx.x*blockDim.x + threadIdx.x;   // 0..131071
    const float4* p4 = (const float4*)(g_h[src] + (size_t)row*WW);
    float ar[12], ai[12];
#pragma unroll
    for(int k=0;k<12;k++){ ar[k]=0.f; ai[k]=0.f; }
    for(int q=0;q<64;q++){
        float4 v = p4[q];
        const float* tt = ty + q*96;
#pragma unroll
        for(int k=0;k<12;k++){
            ar[k] += v.x*tt[2*k]      + v.y*tt[24+2*k]
                   + v.z*tt[48+2*k]   + v.w*tt[72+2*k];
            ai[k] -= v.x*tt[2*k+1]    + v.y*tt[24+2*k+1]
                   + v.z*tt[48+2*k+1] + v.w*tt[72+2*k+1];
        }
    }
    float* o = g_Fy + (size_t)row*24;
#pragma unroll
    for(int k=0;k<12;k++){ o[2*k]=ar[k]; o[2*k+1]=ai[k]; }
}

// ---------------- K2: DFT over x (24 kx modes), one block per (b,c) ----------------
__global__ void k_dftx(){
    __shared__ float fr[HH*MM], fi[HH*MM];
    int bc = blockIdx.x;
    const float* src = g_Fy + (size_t)bc*HH*24;
    for (int i=threadIdx.x; i<HH*MM; i+=288){ fr[i]=src[2*i]; fi[i]=src[2*i+1]; }
    __syncthreads();
    int t = threadIdx.x;               // 0..287 -> (j,ky)
    int j = t/12, ky = t%12;
    const float* tw = g_TX + j*512;
    float sr=0.f, si=0.f;
    for (int xx=0; xx<HH; xx++){
        float c = tw[2*xx], s = tw[2*xx+1];
        float a = fr[xx*12+ky], b = fi[xx*12+ky];
        sr += a*c + b*s;               // F * e^{-i phi}
        si += b*c - a*s;
    }
    size_t o = ((size_t)bc*288 + t)*2;
    g_G[o]=sr; g_G[o+1]=si;
}

// ---------------- K3: complex mode mixing, one block per mode ----------------
__global__ void k_modemix(const float* __restrict__ w1, const float* __restrict__ w2, int layer){
    __shared__ float gr[512], gi[512];     // [b*64+i]
    __shared__ float wr[4096], wi[4096];   // [i*64+o]
    int m = blockIdx.x; int j = m/12, ky = m%12;
    const float* W = (j<12)? w1 : w2;
    int jm = (j<12)? j : (j-12);
    for (int t=threadIdx.x; t<4096; t+=256){
        int i = t>>6, o = t&63;
        size_t idx = (((((size_t)layer*CH + i)*CH + o)*MM + jm)*MM + ky)*2;
        wr[t]=W[idx]; wi[t]=W[idx+1];
    }
    for (int t=threadIdx.x; t<512; t+=256){
        size_t idx = ((size_t)t*288 + m)*2;     // t = b*64+i
        gr[t]=g_G[idx]; gi[t]=g_G[idx+1];
    }
    __syncthreads();
    int t = threadIdx.x;
    int o = t & 63;
#pragma unroll
    for (int bh=0; bh<2; bh++){
        int b = (t>>6) + 4*bh;
        float sr=0.f, si=0.f;
        for (int i=0;i<CH;i++){
            float a = gr[b*64+i], bb = gi[b*64+i];
            float c = wr[i*64+o], d  = wi[i*64+o];
            sr += a*c - bb*d;
            si += a*d + bb*c;
        }
        size_t idx = (((size_t)b*CH + o)*288 + m)*2;
        g_G2[idx]=sr; g_G2[idx+1]=si;
    }
}

// ---------------- K4: inverse over x, one block per (b,o), thread per x ----------------
__global__ void k_invx(){
    __shared__ float jr[288], ji[288];
    int bo = blockIdx.x;
    for (int t=threadIdx.x; t<288; t+=256){
        jr[t]=g_G2[((size_t)bo*288+t)*2];
        ji[t]=g_G2[((size_t)bo*288+t)*2+1];
    }
    __syncthreads();
    int xx = threadIdx.x;
    float er[12], ei[12];
#pragma unroll
    for(int k=0;k<12;k++){ er[k]=0.f; ei[k]=0.f; }
    for (int j=0;j<KXM;j++){
        float c = g_TX[(j*HH+xx)*2], s = g_TX[(j*HH+xx)*2+1];
#pragma unroll
        for (int ky=0;ky<12;ky++){
            float a = jr[j*12+ky], b = ji[j*12+ky];
            er[ky] += a*c - b*s;       // O * e^{+i phi}
            ei[ky] += b*c + a*s;
        }
    }
    const float inv = 1.0f/65536.0f;   // 1/(H*W) from irfft2
    float* o = g_E + (((size_t)bo)*HH + xx)*24;
#pragma unroll
    for (int ky=0;ky<12;ky++){ o[2*ky]=er[ky]*inv; o[2*ky+1]=ei[ky]*inv; }
}

// ---------------- K5: fused (pointwise conv + inverse-y + bias + GELU) ----------------
#define K5_SMEM ((CH*WW + CH*CH + KXM*CH + KXM*WW + CH)*4)

__global__ void k_layer(const float* __restrict__ pw_w, const float* __restrict__ pw_b,
                        int layer, int src, int dogelu){
    extern __shared__ float sm[];
    float* hs  = sm;                 // [i][y]     64*256
    float* ws  = hs + CH*WW;         // [i*64+o]   64*64
    float* es  = ws + CH*CH;         // [k*64+o]   24*64
    float* tys = es + KXM*CH;        // [k*256+y]  24*256
    float* bs  = tys + KXM*WW;       // [o]
    int b = blockIdx.x >> 8, xr = blockIdx.x & 255;
    const float* hin = g_h[src];
    float* hout = g_h[src^1];
    for (int t=threadIdx.x; t<CH*64; t+=256){               // 4096 float4
        int i=t>>6, q=t&63;
        ((float4*)hs)[t] = ((const float4*)(hin + (((size_t)(b*CH+i))<<16) + (xr<<8)))[q];
    }
    for (int t=threadIdx.x; t<CH*CH; t+=256){
        int i=t>>6, o=t&63;
        ws[t] = pw_w[(layer*CH + o)*CH + i];
    }
    for (int t=threadIdx.x; t<KXM*CH; t+=256){
        int k=t>>6, o=t&63;
        es[t] = g_E[(((size_t)(b*CH+o))*HH + xr)*24 + k];
    }
    for (int t=threadIdx.x; t<KXM*WW; t+=256) tys[t]=g_TYinv[t];
    if (threadIdx.x<CH) bs[threadIdx.x]=pw_b[layer*CH+threadIdx.x];
    __syncthreads();
    int ty = threadIdx.x & 63, to = threadIdx.x >> 6;
    float acc[16][4];
#pragma unroll
    for(int a=0;a<16;a++)
#pragma unroll
        for(int c=0;c<4;c++) acc[a][c]=0.f;
    // pointwise conv part: k over 64 input channels
    for (int i=0;i<CH;i++){
        float4 hv = ((const float4*)hs)[i*64 + ty];
        const float* wp = ws + i*64 + to*16;
#pragma unroll
        for (int oo=0;oo<16;oo++){
            float w = wp[oo];
            acc[oo][0] += w*hv.x; acc[oo][1] += w*hv.y;
            acc[oo][2] += w*hv.z; acc[oo][3] += w*hv.w;
        }
    }
    // inverse-y part: 24 more "k" rows (real basis)
    for (int k=0;k<KXM;k++){
        float4 hv = ((const float4*)tys)[k*64 + ty];
        const float* wp = es + k*64 + to*16;
#pragma unroll
        for (int oo=0;oo<16;oo++){
            float w = wp[oo];
            acc[oo][0] += w*hv.x; acc[oo][1] += w*hv.y;
            acc[oo][2] += w*hv.z; acc[oo][3] += w*hv.w;
        }
    }
#pragma unroll
    for (int oo=0;oo<16;oo++){
        int o = to*16+oo;
        float bb = bs[o];
        float4 r;
        r.x = acc[oo][0]+bb; r.y = acc[oo][1]+bb;
        r.z = acc[oo][2]+bb; r.w = acc[oo][3]+bb;
        if (dogelu){
            r.x=gelu_f(r.x); r.y=gelu_f(r.y); r.z=gelu_f(r.z); r.w=gelu_f(r.w);
        }
        ((float4*)(hout + (((size_t)(b*CH+o))<<16) + (xr<<8)))[ty] = r;
    }
}

// ---------------- K6: fused head fc1 -> gelu -> fc2 ----------------
#define K6_SMEM ((CH*WW + CH*FCH + 4*WW)*4)

__global__ void k_head(const float* __restrict__ fc1w, const float* __restrict__ fc1b,
                       const float* __restrict__ fc2w, const float* __restrict__ fc2b,
                       float* __restrict__ out, int src){
    extern __shared__ float sm[];
    float* hs   = sm;                // [i][y]    64*256
    float* w1s  = hs + CH*WW;        // [i*128+f] 64*128
    float* part = w1s + CH*FCH;      // [4][256]
    int b = blockIdx.x>>8, xr = blockIdx.x&255;
    const float* hin = g_h[src];
    for (int t=threadIdx.x; t<CH*64; t+=256){
        int i=t>>6, q=t&63;
        ((float4*)hs)[t] = ((const float4*)(hin + (((size_t)(b*CH+i))<<16) + (xr<<8)))[q];
    }
    for (int t=threadIdx.x; t<CH*FCH; t+=256){
        int i=t>>7, f=t&127;
        w1s[t] = fc1w[f*CH + i];
    }
    __syncthreads();
    int ty = threadIdx.x&63, tf = threadIdx.x>>6;
    float oacc[4]={0.f,0.f,0.f,0.f};
    for (int pass=0; pass<2; pass++){
        int f0 = tf*32 + pass*16;
        float acc[16][4];
#pragma unroll
        for(int a=0;a<16;a++)
#pragma unroll
            for(int c=0;c<4;c++) acc[a][c]=0.f;
        for (int i=0;i<CH;i++){
            float4 hv = ((const float4*)hs)[i*64+ty];
            const float* wp = w1s + i*FCH + f0;
#pragma unroll
            for (int ff=0; ff<16; ff++){
                float w = wp[ff];
                acc[ff][0] += w*hv.x; acc[ff][1] += w*hv.y;
                acc[ff][2] += w*hv.z; acc[ff][3] += w*hv.w;
            }
        }
#pragma unroll
        for (int ff=0; ff<16; ff++){
            float bb = fc1b[f0+ff];
            float c2 = fc2w[f0+ff];
#pragma unroll
            for (int yy=0;yy<4;yy++){
                oacc[yy] += c2 * gelu_f(acc[ff][yy] + bb);
            }
        }
    }
#pragma unroll
    for (int yy=0;yy<4;yy++) part[tf*WW + ty*4+yy] = oacc[yy];
    __syncthreads();
    int y = threadIdx.x;
    float s = part[y] + part[WW+y] + part[2*WW+y] + part[3*WW+y] + fc2b[0];
    out[(((size_t)b)<<16) + (xr<<8) + y] = s;
}

// ---------------- launch ----------------
extern "C" void kernel_launch(void* const* d_in, const int* in_sizes, int n_in,
                              void* d_out, int out_size){
    (void)in_sizes; (void)n_in; (void)out_size;
    const float* x     = (const float*)d_in[0];
    const float* fc0_w = (const float*)d_in[1];
    const float* fc0_b = (const float*)d_in[2];
    const float* w1    = (const float*)d_in[3];
    const float* w2    = (const float*)d_in[4];
    const float* pw_w  = (const float*)d_in[5];
    const float* pw_b  = (const float*)d_in[6];
    const float* fc1_w = (const float*)d_in[7];
    const float* fc1_b = (const float*)d_in[8];
    const float* fc2_w = (const float*)d_in[9];
    const float* fc2_b = (const float*)d_in[10];
    float* out = (float*)d_out;

    cudaFuncSetAttribute(k_layer, cudaFuncAttributeMaxDynamicSharedMemorySize, K5_SMEM);
    cudaFuncSetAttribute(k_head,  cudaFuncAttributeMaxDynamicSharedMemorySize, K6_SMEM);

    k_tables<<<24,256>>>();
    k_lift<<<BATCH*HH,256>>>(x, fc0_w, fc0_b);
    for (int l=0; l<NLAYERS; l++){
        int src = l & 1;
        k_dfty<<<512,256>>>(src);
        k_dftx<<<BATCH*CH,288>>>();
        k_modemix<<<KXM*MM,256>>>(w1, w2, l);
        k_invx<<<BATCH*CH,256>>>();
        k_layer<<<BATCH*HH,256,K5_SMEM>>>(pw_w, pw_b, l, src, (l<NLAYERS-1)?1:0);
    }
    k_head<<<BATCH*HH,256,K6_SMEM>>>(fc1_w, fc1_b, fc2_w, fc2_b, out, 0);
}

// round 2
// speedup vs baseline: 1.1925x; 1.1925x over previous
#include <cuda_runtime.h>
#include <cstdint>
#include <cstddef>

#define BATCH 8
#define CH 64
#define HH 256
#define WW 256
#define MM 12
#define KXM 24
#define NLAYERS 4
#define FCH 128
#define HW (HH*WW)
#define BCHW (BATCH*CH*HW)

// ---------------- device scratch (no runtime allocation allowed) ----------------
__device__ float g_h[2][BCHW];                 // ping-pong activations [b,c,x,y]
__device__ float g_Fy[BATCH*CH*HH*MM*2];       // [b,c,x,ky,(re,im)]
__device__ float g_G [BATCH*CH*KXM*MM*2];      // [b,c, j*12+ky, (re,im)]
__device__ float g_G2[BATCH*CH*KXM*MM*2];      // [b,o, j*12+ky, (re,im)]
__device__ float g_E [BATCH*CH*HH*MM*2];       // [b,o,x, ky,(re,im)]  (x-inverse done, /65536)
__device__ float g_TY[HH*MM*2];                // forward y basis: cos,sin
__device__ float g_TX[KXM*HH*2];               // x twiddles: cos,sin
__device__ float g_TYinv[KXM*HH];              // inverse-y real basis rows [k][y]

__device__ __forceinline__ float gelu_f(float v){
    return 0.5f*v*(1.0f + erff(v*0.70710678118654752f));
}
__device__ __forceinline__ float f2tf32(float x){
    uint32_t r; asm("cvt.rna.tf32.f32 %0, %1;" : "=r"(r) : "f"(x));
    return __uint_as_float(r);
}
__device__ __forceinline__ void mma_tf32(float& d0,float& d1,float& d2,float& d3,
                                         float a0,float a1,float a2,float a3,
                                         float b0,float b1){
    asm volatile("mma.sync.aligned.m16n8k8.row.col.f32.tf32.tf32.f32 "
        "{%0,%1,%2,%3}, {%4,%5,%6,%7}, {%8,%9}, {%0,%1,%2,%3};"
        : "+f"(d0),"+f"(d1),"+f"(d2),"+f"(d3)
        : "r"(__float_as_uint(a0)),"r"(__float_as_uint(a1)),
          "r"(__float_as_uint(a2)),"r"(__float_as_uint(a3)),
          "r"(__float_as_uint(b0)),"r"(__float_as_uint(b1)));
}

// ---------------- twiddle tables ----------------
__global__ void k_tables(){
    int t = blockIdx.x*blockDim.x + threadIdx.x;
    if (t < HH*MM){
        int y = t/MM, ky = t%MM;
        int r = (ky*y) & 255;
        double s,c; sincospi(2.0*r/256.0, &s, &c);
        g_TY[2*t]   = (float)c;
        g_TY[2*t+1] = (float)s;
    }
    if (t < KXM*HH){
        {
            int j = t/HH, xx = t%HH;
            int k = (j<12)? j : (j-24);
            int r = ((k*xx)%256 + 256) & 255;
            double s,c; sincospi(2.0*r/256.0, &s, &c);
            g_TX[2*t]   = (float)c;
            g_TX[2*t+1] = (float)s;
        }
        {
            int kk = t/HH, y = t%HH;
            int ky2 = kk>>1;
            int r2 = (ky2*y) & 255;
            double s2,c2; sincospi(2.0*r2/256.0, &s2, &c2);
            float v;
            if ((kk&1)==0) v = (ky2==0)? 1.0f : 2.0f*(float)c2;
            else           v = (ky2==0)? 0.0f : -2.0f*(float)s2;
            g_TYinv[t] = v;
        }
    }
}

// ---------------- lift ----------------
__global__ void k_lift(const float* __restrict__ x, const float* __restrict__ fw,
                       const float* __restrict__ fb){
    __shared__ float w[CH*3];
    __shared__ float bsh[CH];
    if (threadIdx.x < CH*3) w[threadIdx.x]   = fw[threadIdx.x];
    if (threadIdx.x < CH)   bsh[threadIdx.x] = fb[threadIdx.x];
    __syncthreads();
    int b = blockIdx.x>>8, xr = blockIdx.x&255;
    int y = threadIdx.x;
    float xin = x[(((size_t)b)<<16) + (xr<<8) + y];
    float gx = xr*(1.0f/255.0f), gy = y*(1.0f/255.0f);
    for (int wo=0; wo<CH; wo++){
        float v = w[wo*3]*xin + w[wo*3+1]*gx + w[wo*3+2]*gy + bsh[wo];
        g_h[0][(((size_t)(b*CH+wo))<<16) + (xr<<8) + y] = v;
    }
}

// ---------------- K1: DFT over y (12 modes), float2 twiddles ----------------
__global__ void k_dfty(int src){
    __shared__ float ty[HH*MM*2];
    for (int i=threadIdx.x; i<HH*MM*2; i+=blockDim.x) ty[i]=g_TY[i];
    __syncthreads();
    int row = blockIdx.x*blockDim.x + threadIdx.x;
    const float4* p4 = (const float4*)(g_h[src] + (size_t)row*WW);
    float ar[12], ai[12];
#pragma unroll
    for(int k=0;k<12;k++){ ar[k]=0.f; ai[k]=0.f; }
    for(int q=0;q<64;q++){
        float4 v = p4[q];
        const float2* tt2 = ((const float2*)ty) + q*48;
#pragma unroll
        for(int k=0;k<12;k++){
            float2 c0 = tt2[k],    c1 = tt2[12+k];
            float2 c2 = tt2[24+k], c3 = tt2[36+k];
            ar[k] += v.x*c0.x + v.y*c1.x + v.z*c2.x + v.w*c3.x;
            ai[k] -= v.x*c0.y + v.y*c1.y + v.z*c2.y + v.w*c3.y;
        }
    }
    float* o = g_Fy + (size_t)row*24;
#pragma unroll
    for(int k=0;k<12;k++){ o[2*k]=ar[k]; o[2*k+1]=ai[k]; }
}

// ---------------- K2: DFT over x (24 kx modes), float2 paired loads ----------------
__global__ void k_dftx(){
    __shared__ float2 fc[HH*MM];
    int bc = blockIdx.x;
    const float2* src = (const float2*)(g_Fy + (size_t)bc*HH*24);
    for (int i=threadIdx.x; i<HH*MM; i+=288) fc[i]=src[i];
    __syncthreads();
    int t = threadIdx.x;               // (j,ky)
    int j = t/12, ky = t%12;
    const float2* tw = ((const float2*)g_TX) + j*HH;
    float sr=0.f, si=0.f;
    for (int xx=0; xx<HH; xx++){
        float2 w = __ldg(tw + xx);
        float2 v = fc[xx*12+ky];
        sr += v.x*w.x + v.y*w.y;
        si += v.y*w.x - v.x*w.y;
    }
    size_t o = ((size_t)bc*288 + t)*2;
    g_G[o]=sr; g_G[o+1]=si;
}

// ---------------- K3: complex mode mixing ----------------
__global__ void k_modemix(const float* __restrict__ w1, const float* __restrict__ w2, int layer){
    __shared__ float gr[512], gi[512];
    __shared__ float wr[4096], wi[4096];
    int m = blockIdx.x; int j = m/12, ky = m%12;
    const float* W = (j<12)? w1 : w2;
    int jm = (j<12)? j : (j-12);
    for (int t=threadIdx.x; t<4096; t+=256){
        int i = t>>6, o = t&63;
        size_t idx = (((((size_t)layer*CH + i)*CH + o)*MM + jm)*MM + ky)*2;
        wr[t]=W[idx]; wi[t]=W[idx+1];
    }
    for (int t=threadIdx.x; t<512; t+=256){
        size_t idx = ((size_t)t*288 + m)*2;
        gr[t]=g_G[idx]; gi[t]=g_G[idx+1];
    }
    __syncthreads();
    int t = threadIdx.x;
    int o = t & 63;
#pragma unroll
    for (int bh=0; bh<2; bh++){
        int b = (t>>6) + 4*bh;
        float sr=0.f, si=0.f;
        for (int i=0;i<CH;i++){
            float a = gr[b*64+i], bb = gi[b*64+i];
            float c = wr[i*64+o], d  = wi[i*64+o];
            sr += a*c - bb*d;
            si += a*d + bb*c;
        }
        size_t idx = (((size_t)b*CH + o)*288 + m)*2;
        g_G2[idx]=sr; g_G2[idx+1]=si;
    }
}

// ---------------- K4: inverse over x ----------------
__global__ void k_invx(){
    __shared__ float jr[288], ji[288];
    int bo = blockIdx.x;
    for (int t=threadIdx.x; t<288; t+=256){
        jr[t]=g_G2[((size_t)bo*288+t)*2];
        ji[t]=g_G2[((size_t)bo*288+t)*2+1];
    }
    __syncthreads();
    int xx = threadIdx.x;
    float er[12], ei[12];
#pragma unroll
    for(int k=0;k<12;k++){ er[k]=0.f; ei[k]=0.f; }
    for (int j=0;j<KXM;j++){
        float c = g_TX[(j*HH+xx)*2], s = g_TX[(j*HH+xx)*2+1];
#pragma unroll
        for (int ky=0;ky<12;ky++){
            float a = jr[j*12+ky], b = ji[j*12+ky];
            er[ky] += a*c - b*s;
            ei[ky] += b*c + a*s;
        }
    }
    const float inv = 1.0f/65536.0f;
    float* o = g_E + (((size_t)bo)*HH + xx)*24;
#pragma unroll
    for (int ky=0;ky<12;ky++){ o[2*ky]=er[ky]*inv; o[2*ky+1]=ei[ky]*inv; }
}

// ---------------- K5: fused layer via tf32 mma ----------------
// C[y(256), o(64)] = A[y, k(88)] * B[k, o]   per (b, xr)
// A rows: k<64 -> h channels; k>=64 -> TYinv basis row (k-64)
// B rows: k<64 -> pw_w[o][k];  k>=64 -> E[b,o,xr][k-64]
#define PADY 264
#define PADO 72
#define K5_SMEM ((88*PADY + 88*PADO + CH)*4)

__global__ void __launch_bounds__(512,1)
k_layer(const float* __restrict__ pw_w, const float* __restrict__ pw_b,
        int layer, int src, int dogelu){
    extern __shared__ float sm[];
    float* HA = sm;                  // [88][PADY]   A^T: [k][y]
    float* BS = HA + 88*PADY;        // [88][PADO]   B:   [k][o]
    float* bs = BS + 88*PADO;        // [64]
    int b = blockIdx.x >> 8, xr = blockIdx.x & 255;
    const float* hin = g_h[src];
    float* hout = g_h[src^1];
    int tid = threadIdx.x;

    for (int t=tid; t<CH*64; t+=512){            // 4096 float4 = h rows
        int i=t>>6, q=t&63;
        float4 v = ((const float4*)(hin + (((size_t)(b*CH+i))<<16) + (xr<<8)))[q];
        float* d = HA + i*PADY + q*4;
        d[0]=f2tf32(v.x); d[1]=f2tf32(v.y); d[2]=f2tf32(v.z); d[3]=f2tf32(v.w);
    }
    for (int t=tid; t<KXM*WW; t+=512){           // TYinv rows
        int k=t>>8, y=t&255;
        HA[(64+k)*PADY + y] = f2tf32(g_TYinv[t]);
    }
    for (int t=tid; t<CH*CH; t+=512){            // pw weights (transposed)
        int i=t>>6, o=t&63;
        BS[i*PADO + o] = f2tf32(pw_w[(layer*CH + o)*CH + i]);
    }
    for (int t=tid; t<KXM*CH; t+=512){           // E rows
        int k=t>>6, o=t&63;
        BS[(64+k)*PADO + o] = f2tf32(g_E[(((size_t)(b*CH+o))*HH + xr)*24 + k]);
    }
    if (tid<CH) bs[tid]=pw_b[layer*CH+tid];
    __syncthreads();

    int lane = tid & 31, warp = tid >> 5;
    int g = lane >> 2, t4 = lane & 3;
    int wy = warp >> 2, wo = warp & 3;           // 4 x 4 warp grid
    int y0w = wy*64, o0w = wo*16;

    float c[4][2][4];
#pragma unroll
    for (int mi=0;mi<4;mi++)
#pragma unroll
        for (int ni=0;ni<2;ni++)
#pragma unroll
            for (int r=0;r<4;r++) c[mi][ni][r]=0.f;

    for (int kk=0; kk<11; kk++){
        int k0 = kk*8;
        float b0[2], b1[2];
#pragma unroll
        for (int ni=0;ni<2;ni++){
            int o0 = o0w + ni*8;
            b0[ni] = BS[(k0+t4)*PADO + o0+g];
            b1[ni] = BS[(k0+t4+4)*PADO + o0+g];
        }
#pragma unroll
        for (int mi=0;mi<4;mi++){
            int y0 = y0w + mi*16;
            float a0 = HA[(k0+t4)*PADY   + y0+g];
            float a1 = HA[(k0+t4)*PADY   + y0+g+8];
            float a2 = HA[(k0+t4+4)*PADY + y0+g];
            float a3 = HA[(k0+t4+4)*PADY + y0+g+8];
#pragma unroll
            for (int ni=0;ni<2;ni++){
                mma_tf32(c[mi][ni][0],c[mi][ni][1],c[mi][ni][2],c[mi][ni][3],
                         a0,a1,a2,a3,b0[ni],b1[ni]);
            }
        }
    }

#pragma unroll
    for (int mi=0;mi<4;mi++){
        int y = y0w + mi*16 + g;
#pragma unroll
        for (int ni=0;ni<2;ni++){
            int o = o0w + ni*8 + 2*t4;
            float v0 = c[mi][ni][0] + bs[o];
            float v1 = c[mi][ni][1] + bs[o+1];
            float v2 = c[mi][ni][2] + bs[o];
            float v3 = c[mi][ni][3] + bs[o+1];
            if (dogelu){ v0=gelu_f(v0); v1=gelu_f(v1); v2=gelu_f(v2); v3=gelu_f(v3); }
            float* p0 = hout + (((size_t)(b*CH+o  ))<<16) + (xr<<8);
            float* p1 = hout + (((size_t)(b*CH+o+1))<<16) + (xr<<8);
            p0[y]   = v0;
            p1[y]   = v1;
            p0[y+8] = v2;
            p1[y+8] = v3;
        }
    }
}

// ---------------- K6: fused head via tf32 mma ----------------
// C1[y(256), f(128)] = A[y, i(64)] * W1[i, f]; out[y] = sum_f gelu(C1+b1)*w2[f] + b2
#define PADF 136
#define K6_SMEM ((64*PADY + 64*PADF + 4*WW + 2*FCH)*4)

__global__ void __launch_bounds__(512,1)
k_head(const float* __restrict__ fc1w, const float* __restrict__ fc1b,
       const float* __restrict__ fc2w, const float* __restrict__ fc2b,
       float* __restrict__ out, int src){
    extern __shared__ float sm[];
    float* HA   = sm;                    // [64][PADY]
    float* BS   = HA + 64*PADY;          // [64][PADF]
    float* part = BS + 64*PADF;          // [4][256]
    float* b1s  = part + 4*WW;           // [128]
    float* w2s  = b1s + FCH;             // [128]
    int b = blockIdx.x>>8, xr = blockIdx.x&255;
    const float* hin = g_h[src];
    int tid = threadIdx.x;

    for (int t=tid; t<CH*64; t+=512){
        int i=t>>6, q=t&63;
        float4 v = ((const float4*)(hin + (((size_t)(b*CH+i))<<16) + (xr<<8)))[q];
        float* d = HA + i*PADY + q*4;
        d[0]=f2tf32(v.x); d[1]=f2tf32(v.y); d[2]=f2tf32(v.z); d[3]=f2tf32(v.w);
    }
    for (int t=tid; t<CH*FCH; t+=512){
        int i=t>>7, f=t&127;
        BS[i*PADF + f] = f2tf32(fc1w[f*CH + i]);
    }
    if (tid<FCH){ b1s[tid]=fc1b[tid]; w2s[tid]=fc2w[tid]; }
    __syncthreads();

    int lane = tid & 31, warp = tid >> 5;
    int g = lane >> 2, t4 = lane & 3;
    int wy = warp >> 2, wf = warp & 3;
    int y0w = wy*64, f0w = wf*32;

    float c[4][4][4];
#pragma unroll
    for (int mi=0;mi<4;mi++)
#pragma unroll
        for (int ni=0;ni<4;ni++)
#pragma unroll
            for (int r=0;r<4;r++) c[mi][ni][r]=0.f;

    for (int kk=0; kk<8; kk++){
        int k0 = kk*8;
        float b0[4], b1[4];
#pragma unroll
        for (int ni=0;ni<4;ni++){
            int f0 = f0w + ni*8;
            b0[ni] = BS[(k0+t4)*PADF + f0+g];
            b1[ni] = BS[(k0+t4+4)*PADF + f0+g];
        }
#pragma unroll
        for (int mi=0;mi<4;mi++){
            int y0 = y0w + mi*16;
            float a0 = HA[(k0+t4)*PADY   + y0+g];
            float a1 = HA[(k0+t4)*PADY   + y0+g+8];
            float a2 = HA[(k0+t4+4)*PADY + y0+g];
            float a3 = HA[(k0+t4+4)*PADY + y0+g+8];
#pragma unroll
            for (int ni=0;ni<4;ni++){
                mma_tf32(c[mi][ni][0],c[mi][ni][1],c[mi][ni][2],c[mi][ni][3],
                         a0,a1,a2,a3,b0[ni],b1[ni]);
            }
        }
    }

#pragma unroll
    for (int mi=0;mi<4;mi++){
        float s0=0.f, s1=0.f;
#pragma unroll
        for (int ni=0;ni<4;ni++){
            int f = f0w + ni*8 + 2*t4;
            float ba = b1s[f], bb = b1s[f+1];
            float wa = w2s[f], wb = w2s[f+1];
            s0 += gelu_f(c[mi][ni][0]+ba)*wa + gelu_f(c[mi][ni][1]+bb)*wb;
            s1 += gelu_f(c[mi][ni][2]+ba)*wa + gelu_f(c[mi][ni][3]+bb)*wb;
        }
        s0 += __shfl_xor_sync(0xffffffffu, s0, 1);
        s0 += __shfl_xor_sync(0xffffffffu, s0, 2);
        s1 += __shfl_xor_sync(0xffffffffu, s1, 1);
        s1 += __shfl_xor_sync(0xffffffffu, s1, 2);
        if (t4==0){
            int y = y0w + mi*16 + g;
            part[wf*WW + y]   = s0;
            part[wf*WW + y+8] = s1;
        }
    }
    __syncthreads();
    if (tid < WW){
        int y = tid;
        float s = part[y] + part[WW+y] + part[2*WW+y] + part[3*WW+y] + fc2b[0];
        out[(((size_t)b)<<16) + (xr<<8) + y] = s;
    }
}

// ---------------- launch ----------------
extern "C" void kernel_launch(void* const* d_in, const int* in_sizes, int n_in,
                              void* d_out, int out_size){
    (void)in_sizes; (void)n_in; (void)out_size;
    const float* x     = (const float*)d_in[0];
    const float* fc0_w = (const float*)d_in[1];
    const float* fc0_b = (const float*)d_in[2];
    const float* w1    = (const float*)d_in[3];
    const float* w2    = (const float*)d_in[4];
    const float* pw_w  = (const float*)d_in[5];
    const float* pw_b  = (const float*)d_in[6];
    const float* fc1_w = (const float*)d_in[7];
    const float* fc1_b = (const float*)d_in[8];
    const float* fc2_w = (const float*)d_in[9];
    const float* fc2_b = (const float*)d_in[10];
    float* out = (float*)d_out;

    cudaFuncSetAttribute(k_layer, cudaFuncAttributeMaxDynamicSharedMemorySize, K5_SMEM);
    cudaFuncSetAttribute(k_head,  cudaFuncAttributeMaxDynamicSharedMemorySize, K6_SMEM);

    k_tables<<<24,256>>>();
    k_lift<<<BATCH*HH,256>>>(x, fc0_w, fc0_b);
    for (int l=0; l<NLAYERS; l++){
        int src = l & 1;
        k_dfty<<<512,256>>>(src);
        k_dftx<<<BATCH*CH,288>>>();
        k_modemix<<<KXM*MM,256>>>(w1, w2, l);
        k_invx<<<BATCH*CH,256>>>();
        k_layer<<<BATCH*HH,512,K5_SMEM>>>(pw_w, pw_b, l, src, (l<NLAYERS-1)?1:0);
    }
    k_head<<<BATCH*HH,512,K6_SMEM>>>(fc1_w, fc1_b, fc2_w, fc2_b, out, 0);
}

// round 3
// speedup vs baseline: 1.3738x; 1.1520x over previous
#include <cuda_runtime.h>
#include <cstdint>
#include <cstddef>

#define BATCH 8
#define CH 64
#define HH 256
#define WW 256
#define MM 12
#define KXM 24
#define NLAYERS 4
#define FCH 128
#define HW (HH*WW)
#define BCHW (BATCH*CH*HW)

// ---------------- device scratch ----------------
__device__ float g_h[2][BCHW];                 // ping-pong activations [b,c,x,y]
__device__ float g_Fy[BATCH*CH*HH*MM*2];       // [b,c,x][ky,(re,im)]
__device__ float g_G [BATCH*CH*KXM*MM*2];
__device__ float g_G2[BATCH*CH*KXM*MM*2];
__device__ float g_E [BATCH*CH*HH*MM*2];       // [b,o,x][ky,(re,im)] (/65536 applied)
__device__ float g_TY[HH*MM*2];                // forward y basis
__device__ float g_TX[KXM*HH*2];               // x twiddles
__device__ float g_TYinv[KXM*HH];              // inverse-y real basis [k][y]
// pre-fragmented MMA operands (tf32)
__device__ float g_TYF[3*16*32*4];             // A-frags for TYinv (kk 0..2 rel)
__device__ float g_PWF[NLAYERS*8*8*32*2];      // B-frags for pw weights per layer
__device__ float g_FC1F[8*16*32*2];            // B-frags for fc1 weights

__device__ __forceinline__ float gelu_f(float v){
    return 0.5f*v*(1.0f + erff(v*0.70710678118654752f));
}
__device__ __forceinline__ float f2tf32(float x){
    uint32_t r; asm("cvt.rna.tf32.f32 %0, %1;" : "=r"(r) : "f"(x));
    return __uint_as_float(r);
}
__device__ __forceinline__ void mma_tf32(float& d0,float& d1,float& d2,float& d3,
                                         float a0,float a1,float a2,float a3,
                                         float b0,float b1){
    asm volatile("mma.sync.aligned.m16n8k8.row.col.f32.tf32.tf32.f32 "
        "{%0,%1,%2,%3}, {%4,%5,%6,%7}, {%8,%9}, {%0,%1,%2,%3};"
        : "+f"(d0),"+f"(d1),"+f"(d2),"+f"(d3)
        : "r"(__float_as_uint(a0)),"r"(__float_as_uint(a1)),
          "r"(__float_as_uint(a2)),"r"(__float_as_uint(a3)),
          "r"(__float_as_uint(b0)),"r"(__float_as_uint(b1)));
}

// ---------------- twiddle tables ----------------
__global__ void k_tables(){
    int t = blockIdx.x*blockDim.x + threadIdx.x;
    if (t < HH*MM){
        int y = t/MM, ky = t%MM;
        int r = (ky*y) & 255;
        double s,c; sincospi(2.0*r/256.0, &s, &c);
        g_TY[2*t]   = (float)c;
        g_TY[2*t+1] = (float)s;
    }
    if (t < KXM*HH){
        {
            int j = t/HH, xx = t%HH;
            int k = (j<12)? j : (j-24);
            int r = ((k*xx)%256 + 256) & 255;
            double s,c; sincospi(2.0*r/256.0, &s, &c);
            g_TX[2*t]   = (float)c;
            g_TX[2*t+1] = (float)s;
        }
        {
            int kk = t/HH, y = t%HH;
            int ky2 = kk>>1;
            int r2 = (ky2*y) & 255;
            double s2,c2; sincospi(2.0*r2/256.0, &s2, &c2);
            float v;
            if ((kk&1)==0) v = (ky2==0)? 1.0f : 2.0f*(float)c2;
            else           v = (ky2==0)? 0.0f : -2.0f*(float)s2;
            g_TYinv[t] = v;
        }
    }
}

// ---------------- fragment pre-pack (TYinv A-frags, pw + fc1 B-frags) ----------------
__global__ void k_frw(const float* __restrict__ pw_w, const float* __restrict__ fc1w){
    int t = blockIdx.x*blockDim.x + threadIdx.x;
    if (t < 6144){                                  // TYinv A-frags
        int k = t>>8, y = t&255;                    // k' = 0..23
        float v = g_TYinv[k*256 + y];
        int kk=k>>3, kin=k&7, t4=kin&3, kh=kin>>2;
        int yt=y>>4, yin=y&15, g=yin&7, half=yin>>3;
        g_TYF[(((kk*16+yt)<<5) + ((g<<2)|t4))*4 + ((kh<<1)|half)] = f2tf32(v);
    } else if (t < 6144+16384){                     // pw B-frags
        int u = t - 6144;
        int layer = u>>12; int v = u&4095;
        int k = v&63, o = v>>6;
        float w = pw_w[(layer*CH+o)*CH + k];
        int kk=k>>3, kin=k&7, t4=kin&3, kh=kin>>2;
        int ot=o>>3, g=o&7;
        g_PWF[layer*4096 + (((kk*8+ot)<<5)+((g<<2)|t4))*2 + kh] = f2tf32(w);
    } else if (t < 6144+16384+8192){                // fc1 B-frags
        int u = t - 6144 - 16384;
        int i = u&63, f = u>>6;
        float w = fc1w[f*CH + i];
        int kk=i>>3, kin=i&7, t4=kin&3, kh=kin>>2;
        int ot=f>>3, g=f&7;
        g_FC1F[(((kk*16+ot)<<5)+((g<<2)|t4))*2 + kh] = f2tf32(w);
    }
}

// ---------------- lift ----------------
__global__ void k_lift(const float* __restrict__ x, const float* __restrict__ fw,
                       const float* __restrict__ fb){
    __shared__ float w[CH*3];
    __shared__ float bsh[CH];
    if (threadIdx.x < CH*3) w[threadIdx.x]   = fw[threadIdx.x];
    if (threadIdx.x < CH)   bsh[threadIdx.x] = fb[threadIdx.x];
    __syncthreads();
    int b = blockIdx.x>>8, xr = blockIdx.x&255;
    int y = threadIdx.x;
    float xin = x[(((size_t)b)<<16) + (xr<<8) + y];
    float gx = xr*(1.0f/255.0f), gy = y*(1.0f/255.0f);
    for (int wo=0; wo<CH; wo++){
        float v = w[wo*3]*xin + w[wo*3+1]*gx + w[wo*3+2]*gy + bsh[wo];
        g_h[0][(((size_t)(b*CH+wo))<<16) + (xr<<8) + y] = v;
    }
}

// ---------------- K1: DFT over y (12 modes), 2 rows per thread ----------------
__global__ void __launch_bounds__(128) k_dfty(int src){
    __shared__ float ty[HH*MM*2];
    for (int i=threadIdx.x; i<HH*MM*2; i+=128) ty[i]=g_TY[i];
    __syncthreads();
    int rb = (blockIdx.x*128 + threadIdx.x)*2;
    const float4* p0 = (const float4*)(g_h[src] + (size_t)rb*WW);
    const float4* p1 = p0 + 64;
    float a0r[12],a0i[12],a1r[12],a1i[12];
#pragma unroll
    for(int k=0;k<12;k++){ a0r[k]=0.f; a0i[k]=0.f; a1r[k]=0.f; a1i[k]=0.f; }
    for(int q=0;q<64;q++){
        float4 u = p0[q];
        float4 v = p1[q];
        const float2* tt = ((const float2*)ty) + q*48;
#pragma unroll
        for(int k=0;k<12;k++){
            float2 c0 = tt[k],    c1 = tt[12+k];
            float2 c2 = tt[24+k], c3 = tt[36+k];
            a0r[k] += u.x*c0.x + u.y*c1.x + u.z*c2.x + u.w*c3.x;
            a0i[k] -= u.x*c0.y + u.y*c1.y + u.z*c2.y + u.w*c3.y;
            a1r[k] += v.x*c0.x + v.y*c1.x + v.z*c2.x + v.w*c3.x;
            a1i[k] -= v.x*c0.y + v.y*c1.y + v.z*c2.y + v.w*c3.y;
        }
    }
    float* o0 = g_Fy + (size_t)rb*24;
    float* o1 = o0 + 24;
#pragma unroll
    for(int k=0;k<12;k++){
        o0[2*k]=a0r[k]; o0[2*k+1]=a0i[k];
        o1[2*k]=a1r[k]; o1[2*k+1]=a1i[k];
    }
}

// ---------------- K2: DFT over x, twiddles in smem, unrolled ----------------
#define DFTX_SMEM ((KXM*HH*2 + HH*MM*2)*4)
__global__ void k_dftx(){
    extern __shared__ float sm[];
    float2* tws = (float2*)sm;           // [24][256]
    float2* fcs = tws + KXM*HH;          // [256][12]
    int bc = blockIdx.x;
    const float2* src = (const float2*)(g_Fy + (size_t)bc*HH*24);
    for (int i=threadIdx.x; i<KXM*HH; i+=288) tws[i]=((const float2*)g_TX)[i];
    for (int i=threadIdx.x; i<HH*MM; i+=288)  fcs[i]=src[i];
    __syncthreads();
    int t = threadIdx.x;               // (j,ky)
    int j = t/12, ky = t%12;
    const float2* tw = tws + j*HH;
    float sr=0.f, si=0.f;
#pragma unroll 4
    for (int xx=0; xx<HH; xx++){
        float2 w = tw[xx];
        float2 v = fcs[xx*12+ky];
        sr += v.x*w.x + v.y*w.y;
        si += v.y*w.x - v.x*w.y;
    }
    size_t o = ((size_t)bc*288 + t)*2;
    g_G[o]=sr; g_G[o+1]=si;
}

// ---------------- K3: complex mode mixing ----------------
__global__ void k_modemix(const float* __restrict__ w1, const float* __restrict__ w2, int layer){
    __shared__ float gr[512], gi[512];
    __shared__ float wr[4096], wi[4096];
    int m = blockIdx.x; int j = m/12, ky = m%12;
    const float* W = (j<12)? w1 : w2;
    int jm = (j<12)? j : (j-12);
    for (int t=threadIdx.x; t<4096; t+=256){
        int i = t>>6, o = t&63;
        size_t idx = (((((size_t)layer*CH + i)*CH + o)*MM + jm)*MM + ky)*2;
        wr[t]=W[idx]; wi[t]=W[idx+1];
    }
    for (int t=threadIdx.x; t<512; t+=256){
        size_t idx = ((size_t)t*288 + m)*2;
        gr[t]=g_G[idx]; gi[t]=g_G[idx+1];
    }
    __syncthreads();
    int t = threadIdx.x;
    int o = t & 63;
#pragma unroll
    for (int bh=0; bh<2; bh++){
        int b = (t>>6) + 4*bh;
        float sr=0.f, si=0.f;
        for (int i=0;i<CH;i++){
            float a = gr[b*64+i], bb = gi[b*64+i];
            float c = wr[i*64+o], d  = wi[i*64+o];
            sr += a*c - bb*d;
            si += a*d + bb*c;
        }
        size_t idx = (((size_t)b*CH + o)*288 + m)*2;
        g_G2[idx]=sr; g_G2[idx+1]=si;
    }
}

// ---------------- K4: inverse over x ----------------
__global__ void k_invx(){
    __shared__ float jr[288], ji[288];
    int bo = blockIdx.x;
    for (int t=threadIdx.x; t<288; t+=256){
        jr[t]=g_G2[((size_t)bo*288+t)*2];
        ji[t]=g_G2[((size_t)bo*288+t)*2+1];
    }
    __syncthreads();
    int xx = threadIdx.x;
    float er[12], ei[12];
#pragma unroll
    for(int k=0;k<12;k++){ er[k]=0.f; ei[k]=0.f; }
    for (int j=0;j<KXM;j++){
        float c = g_TX[(j*HH+xx)*2], s = g_TX[(j*HH+xx)*2+1];
#pragma unroll
        for (int ky=0;ky<12;ky++){
            float a = jr[j*12+ky], b = ji[j*12+ky];
            er[ky] += a*c - b*s;
            ei[ky] += b*c + a*s;
        }
    }
    const float inv = 1.0f/65536.0f;
    float* o = g_E + (((size_t)bo)*HH + xx)*24;
#pragma unroll
    for (int ky=0;ky<12;ky++){ o[2*ky]=er[ky]*inv; o[2*ky+1]=ei[ky]*inv; }
}

// ---------------- K5: fused layer, fragment-packed tf32 mma ----------------
// C[y(256), o(64)] = A[y, k(88)] * B[k, o] per (b, xr); kk 0..7 = h/pw, 8..10 = TYinv/E
#define NKK5 11
#define AF5_F (NKK5*16*32*4)     /* 22528 floats */
#define BF5_F (NKK5*8*32*2)      /* 5632 floats */
#define K5_SMEM ((AF5_F + BF5_F + 64)*4)

__global__ void __launch_bounds__(256)
k_layer(const float* __restrict__ pw_b, int layer, int src, int dogelu){
    extern __shared__ float sm[];
    float* AF = sm;
    float* BF = AF + AF5_F;
    float* bs = BF + BF5_F;
    int b = blockIdx.x >> 8, xr = blockIdx.x & 255;
    const float* hin = g_h[src];
    float* hout = g_h[src^1];
    int tid = threadIdx.x;

    // h channels -> A frags (kk 0..7)
    for (int t=tid; t<CH*64; t+=256){
        int i=t>>6, q=t&63;
        float4 v = ((const float4*)(hin + (((size_t)(b*CH+i))<<16) + (xr<<8)))[q];
        int kk=i>>3, kin=i&7, t4=kin&3, kh=kin>>2;
        float vv[4] = {v.x, v.y, v.z, v.w};
#pragma unroll
        for (int d=0; d<4; d++){
            int y = q*4+d; int yt=y>>4, yin=y&15, g=yin&7, half=yin>>3;
            AF[(((kk*16+yt)<<5)+((g<<2)|t4))*4 + ((kh<<1)|half)] = f2tf32(vv[d]);
        }
    }
    // TYinv frags -> AF kk 8..10 (straight copy)
    for (int t=tid; t<1536; t+=256)
        ((float4*)AF)[4096 + t] = ((const float4*)g_TYF)[t];
    // pw frags -> BF kk 0..7 (straight copy)
    for (int t=tid; t<1024; t+=256)
        ((float4*)BF)[t] = ((const float4*)(g_PWF + layer*4096))[t];
    // E -> B frags kk 8..10
    for (int t=tid; t<KXM*CH; t+=256){
        int o = t/24, ke = t%24;
        float v = g_E[(((size_t)(b*CH+o))*HH + xr)*24 + ke];
        int kk=8+(ke>>3), kin=ke&7, t4=kin&3, kh=kin>>2;
        int ot=o>>3, g=o&7;
        BF[(((kk*8+ot)<<5)+((g<<2)|t4))*2 + kh] = f2tf32(v);
    }
    if (tid<CH) bs[tid]=pw_b[layer*CH+tid];
    __syncthreads();

    int lane = tid & 31, warp = tid >> 5;
    int wy = warp >> 1, wo = warp & 1;        // 4 x 2 warp grid, tile 64y x 32o

    float c[4][4][4];
#pragma unroll
    for (int mi=0;mi<4;mi++)
#pragma unroll
        for (int ni=0;ni<4;ni++)
#pragma unroll
            for (int r=0;r<4;r++) c[mi][ni][r]=0.f;

    for (int kk=0; kk<NKK5; kk++){
        float2 bf[4];
#pragma unroll
        for (int ni=0;ni<4;ni++){
            int ot = wo*4+ni;
            bf[ni] = ((const float2*)BF)[((kk*8+ot)<<5)+lane];
        }
#pragma unroll
        for (int mi=0;mi<4;mi++){
            int yt = wy*4+mi;
            float4 af = ((const float4*)AF)[((kk*16+yt)<<5)+lane];
#pragma unroll
            for (int ni=0;ni<4;ni++){
                mma_tf32(c[mi][ni][0],c[mi][ni][1],c[mi][ni][2],c[mi][ni][3],
                         af.x,af.y,af.z,af.w, bf[ni].x, bf[ni].y);
            }
        }
    }

    int g = lane>>2, t4 = lane&3;
#pragma unroll
    for (int mi=0;mi<4;mi++){
        int y = (wy*4+mi)*16 + g;
#pragma unroll
        for (int ni=0;ni<4;ni++){
            int o = (wo*4+ni)*8 + 2*t4;
            float bb0 = bs[o], bb1 = bs[o+1];
            float v0 = c[mi][ni][0] + bb0;
            float v1 = c[mi][ni][1] + bb1;
            float v2 = c[mi][ni][2] + bb0;
            float v3 = c[mi][ni][3] + bb1;
            if (dogelu){ v0=gelu_f(v0); v1=gelu_f(v1); v2=gelu_f(v2); v3=gelu_f(v3); }
            float* p0 = hout + (((size_t)(b*CH+o  ))<<16) + (xr<<8);
            float* p1 = hout + (((size_t)(b*CH+o+1))<<16) + (xr<<8);
            p0[y]   = v0;
            p1[y]   = v1;
            p0[y+8] = v2;
            p1[y+8] = v3;
        }
    }
}

// ---------------- K6: fused head, fragment-packed tf32 mma ----------------
#define NKK6 8
#define AF6_F (NKK6*16*32*4)     /* 16384 floats */
#define BF6_F (NKK6*16*32*2)     /* 8192 floats */
#define K6_SMEM ((AF6_F + BF6_F + 2*WW + 2*FCH)*4)

__global__ void __launch_bounds__(256)
k_head(const float* __restrict__ fc1b, const float* __restrict__ fc2w,
       const float* __restrict__ fc2b, float* __restrict__ out, int src){
    extern __shared__ float sm[];
    float* AF   = sm;
    float* BF   = AF + AF6_F;
    float* part = BF + BF6_F;            // [2][256]
    float* b1s  = part + 2*WW;           // [128]
    float* w2s  = b1s + FCH;             // [128]
    int b = blockIdx.x>>8, xr = blockIdx.x&255;
    const float* hin = g_h[src];
    int tid = threadIdx.x;

    for (int t=tid; t<CH*64; t+=256){
        int i=t>>6, q=t&63;
        float4 v = ((const float4*)(hin + (((size_t)(b*CH+i))<<16) + (xr<<8)))[q];
        int kk=i>>3, kin=i&7, t4=kin&3, kh=kin>>2;
        float vv[4] = {v.x, v.y, v.z, v.w};
#pragma unroll
        for (int d=0; d<4; d++){
            int y = q*4+d; int yt=y>>4, yin=y&15, g=yin&7, half=yin>>3;
            AF[(((kk*16+yt)<<5)+((g<<2)|t4))*4 + ((kh<<1)|half)] = f2tf32(vv[d]);
        }
    }
    for (int t=tid; t<2048; t+=256)
        ((float4*)BF)[t] = ((const float4*)g_FC1F)[t];
    if (tid<FCH){ b1s[tid]=fc1b[tid]; w2s[tid]=fc2w[tid]; }
    __syncthreads();

    int lane = tid & 31, warp = tid >> 5;
    int wy = warp >> 1, wf = warp & 1;        // 4 x 2, tile 64y x 64f

    float c[4][8][4];
#pragma unroll
    for (int mi=0;mi<4;mi++)
#pragma unroll
        for (int ni=0;ni<8;ni++)
#pragma unroll
            for (int r=0;r<4;r++) c[mi][ni][r]=0.f;

    for (int kk=0; kk<NKK6; kk++){
        float2 bf[8];
#pragma unroll
        for (int ni=0;ni<8;ni++){
            int ot = wf*8+ni;
            bf[ni] = ((const float2*)BF)[((kk*16+ot)<<5)+lane];
        }
#pragma unroll
        for (int mi=0;mi<4;mi++){
            int yt = wy*4+mi;
            float4 af = ((const float4*)AF)[((kk*16+yt)<<5)+lane];
#pragma unroll
            for (int ni=0;ni<8;ni++){
                mma_tf32(c[mi][ni][0],c[mi][ni][1],c[mi][ni][2],c[mi][ni][3],
                         af.x,af.y,af.z,af.w, bf[ni].x, bf[ni].y);
            }
        }
    }

    int g = lane>>2, t4 = lane&3;
#pragma unroll
    for (int mi=0;mi<4;mi++){
        float s0=0.f, s1=0.f;
#pragma unroll
        for (int ni=0;ni<8;ni++){
            int f = (wf*8+ni)*8 + 2*t4;
            float ba = b1s[f], bb = b1s[f+1];
            float wa = w2s[f], wb = w2s[f+1];
            s0 += gelu_f(c[mi][ni][0]+ba)*wa + gelu_f(c[mi][ni][1]+bb)*wb;
            s1 += gelu_f(c[mi][ni][2]+ba)*wa + gelu_f(c[mi][ni][3]+bb)*wb;
        }
        s0 += __shfl_xor_sync(0xffffffffu, s0, 1);
        s0 += __shfl_xor_sync(0xffffffffu, s0, 2);
        s1 += __shfl_xor_sync(0xffffffffu, s1, 1);
        s1 += __shfl_xor_sync(0xffffffffu, s1, 2);
        if (t4==0){
            int y = (wy*4+mi)*16 + g;
            part[wf*WW + y]   = s0;
            part[wf*WW + y+8] = s1;
        }
    }
    __syncthreads();
    {
        int y = tid;
        float s = part[y] + part[WW+y] + fc2b[0];
        out[(((size_t)b)<<16) + (xr<<8) + y] = s;
    }
}

// ---------------- launch ----------------
extern "C" void kernel_launch(void* const* d_in, const int* in_sizes, int n_in,
                              void* d_out, int out_size){
    (void)in_sizes; (void)n_in; (void)out_size;
    const float* x     = (const float*)d_in[0];
    const float* fc0_w = (const float*)d_in[1];
    const float* fc0_b = (const float*)d_in[2];
    const float* w1    = (const float*)d_in[3];
    const float* w2    = (const float*)d_in[4];
    const float* pw_w  = (const float*)d_in[5];
    const float* pw_b  = (const float*)d_in[6];
    const float* fc1_w = (const float*)d_in[7];
    const float* fc1_b = (const float*)d_in[8];
    const float* fc2_w = (const float*)d_in[9];
    const float* fc2_b = (const float*)d_in[10];
    float* out = (float*)d_out;

    cudaFuncSetAttribute(k_layer, cudaFuncAttributeMaxDynamicSharedMemorySize, K5_SMEM);
    cudaFuncSetAttribute(k_head,  cudaFuncAttributeMaxDynamicSharedMemorySize, K6_SMEM);
    cudaFuncSetAttribute(k_dftx,  cudaFuncAttributeMaxDynamicSharedMemorySize, DFTX_SMEM);

    k_tables<<<24,256>>>();
    k_frw<<<120,256>>>(pw_w, fc1_w);
    k_lift<<<BATCH*HH,256>>>(x, fc0_w, fc0_b);
    for (int l=0; l<NLAYERS; l++){
        int src = l & 1;
        k_dfty<<<512,128>>>(src);
        k_dftx<<<BATCH*CH,288,DFTX_SMEM>>>();
        k_modemix<<<KXM*MM,256>>>(w1, w2, l);
        k_invx<<<BATCH*CH,256>>>();
        k_layer<<<BATCH*HH,256,K5_SMEM>>>(pw_b, l, src, (l<NLAYERS-1)?1:0);
    }
    k_head<<<BATCH*HH,256,K6_SMEM>>>(fc1_b, fc2_w, fc2_b, out, 0);
}

// round 4
// speedup vs baseline: 1.6079x; 1.1703x over previous
#include <cuda_runtime.h>
#include <cstdint>
#include <cstddef>

#define BATCH 8
#define CH 64
#define HH 256
#define WW 256
#define MM 12
#define KXM 24
#define NLAYERS 4
#define FCH 128
#define HW (HH*WW)
#define BCHW (BATCH*CH*HW)
#define PADH 260

// ---------------- device scratch ----------------
__device__ float g_h[2][BCHW];                 // ping-pong activations [b,c,x,y]
__device__ float g_Fy[BATCH*CH*HH*MM*2];       // [b,c,x][ky,(re,im)]
__device__ float g_G [BATCH*CH*KXM*MM*2];
__device__ float g_G2[BATCH*CH*KXM*MM*2];
__device__ float g_E [BATCH*CH*HH*MM*2];       // [b,o,x][ky,(re,im)] (/65536 applied)
__device__ float g_TY[HH*MM*2];                // forward y basis (unused by hot path now)
__device__ float g_TX[KXM*HH*2];               // x twiddles
__device__ float g_TYinv[KXM*HH];              // inverse-y real basis [k][y]
// pre-fragmented MMA operands (tf32)
__device__ float g_TYF[3*16*32*4];             // A-frags for TYinv (kk 8..10 of k_layer)
__device__ float g_PWF[NLAYERS*8*8*32*2];      // B-frags for pw weights per layer
__device__ float g_FC1F[8*16*32*2];            // B-frags for fc1 weights
__device__ float g_TYBF[32*3*32*2];            // B-frags for forward y-DFT basis

__device__ __forceinline__ float gelu_f(float v){
    return 0.5f*v*(1.0f + erff(v*0.70710678118654752f));
}
__device__ __forceinline__ float f2tf32(float x){
    uint32_t r; asm("cvt.rna.tf32.f32 %0, %1;" : "=r"(r) : "f"(x));
    return __uint_as_float(r);
}
__device__ __forceinline__ void mma_tf32(float& d0,float& d1,float& d2,float& d3,
                                         float a0,float a1,float a2,float a3,
                                         float b0,float b1){
    asm volatile("mma.sync.aligned.m16n8k8.row.col.f32.tf32.tf32.f32 "
        "{%0,%1,%2,%3}, {%4,%5,%6,%7}, {%8,%9}, {%0,%1,%2,%3};"
        : "+f"(d0),"+f"(d1),"+f"(d2),"+f"(d3)
        : "r"(__float_as_uint(a0)),"r"(__float_as_uint(a1)),
          "r"(__float_as_uint(a2)),"r"(__float_as_uint(a3)),
          "r"(__float_as_uint(b0)),"r"(__float_as_uint(b1)));
}

// ---------------- fused y-DFT epilogue ----------------
// Fy[o(64), n(24)] = HS[o, y(256)] * Bt[y, n];  n=2k -> cos, n=2k+1 -> -sin
__device__ __forceinline__ void dft_epi(const float* __restrict__ HS, int b, int xr,
                                        int warp, int lane){
    if (warp >= 4) return;
    int g = lane>>2, t4 = lane&3;
    int mt = warp;
    float c[3][4];
#pragma unroll
    for (int nt=0;nt<3;nt++)
#pragma unroll
        for (int r=0;r<4;r++) c[nt][r]=0.f;
    const float2* TB = (const float2*)g_TYBF;
    for (int kk=0; kk<32; kk++){
        float a0 = HS[(mt*16+g  )*PADH + kk*8+t4];
        float a1 = HS[(mt*16+g+8)*PADH + kk*8+t4];
        float a2 = HS[(mt*16+g  )*PADH + kk*8+t4+4];
        float a3 = HS[(mt*16+g+8)*PADH + kk*8+t4+4];
#pragma unroll
        for (int nt=0;nt<3;nt++){
            float2 bf = __ldg(TB + (kk*3+nt)*32 + lane);
            mma_tf32(c[nt][0],c[nt][1],c[nt][2],c[nt][3], a0,a1,a2,a3, bf.x,bf.y);
        }
    }
    float2* Fy2 = (float2*)g_Fy;
    int o = mt*16+g;
#pragma unroll
    for (int nt=0;nt<3;nt++){
        size_t base = ((size_t)(b*CH+o)*HH + xr)*12 + nt*4 + t4;
        Fy2[base]              = make_float2(c[nt][0], c[nt][1]);
        Fy2[base + 8*HH*12]    = make_float2(c[nt][2], c[nt][3]);   // o+8
    }
}

// ---------------- twiddle tables ----------------
__global__ void k_tables(){
    int t = blockIdx.x*blockDim.x + threadIdx.x;
    if (t < HH*MM){
        int y = t/MM, ky = t%MM;
        int r = (ky*y) & 255;
        double s,c; sincospi(2.0*r/256.0, &s, &c);
        g_TY[2*t]   = (float)c;
        g_TY[2*t+1] = (float)s;
    }
    if (t < KXM*HH){
        {
            int j = t/HH, xx = t%HH;
            int k = (j<12)? j : (j-24);
            int r = ((k*xx)%256 + 256) & 255;
            double s,c; sincospi(2.0*r/256.0, &s, &c);
            g_TX[2*t]   = (float)c;
            g_TX[2*t+1] = (float)s;
        }
        {
            int kk = t/HH, y = t%HH;
            int ky2 = kk>>1;
            int r2 = (ky2*y) & 255;
            double s2,c2; sincospi(2.0*r2/256.0, &s2, &c2);
            float v;
            if ((kk&1)==0) v = (ky2==0)? 1.0f : 2.0f*(float)c2;
            else           v = (ky2==0)? 0.0f : -2.0f*(float)s2;
            g_TYinv[t] = v;
        }
    }
}

// ---------------- fragment pre-pack ----------------
__global__ void k_frw(const float* __restrict__ pw_w, const float* __restrict__ fc1w){
    int t = blockIdx.x*blockDim.x + threadIdx.x;
    if (t < 6144){                                  // TYinv A-frags
        int k = t>>8, y = t&255;
        float v = g_TYinv[k*256 + y];
        int kk=k>>3, kin=k&7, t4=kin&3, kh=kin>>2;
        int yt=y>>4, yin=y&15, g=yin&7, half=yin>>3;
        g_TYF[(((kk*16+yt)<<5) + ((g<<2)|t4))*4 + ((kh<<1)|half)] = f2tf32(v);
    } else if (t < 6144+16384){                     // pw B-frags
        int u = t - 6144;
        int layer = u>>12; int v = u&4095;
        int k = v&63, o = v>>6;
        float w = pw_w[(layer*CH+o)*CH + k];
        int kk=k>>3, kin=k&7, t4=kin&3, kh=kin>>2;
        int ot=o>>3, g=o&7;
        g_PWF[layer*4096 + (((kk*8+ot)<<5)+((g<<2)|t4))*2 + kh] = f2tf32(w);
    } else if (t < 6144+16384+8192){                // fc1 B-frags
        int u = t - 6144 - 16384;
        int i = u&63, f = u>>6;
        float w = fc1w[f*CH + i];
        int kk=i>>3, kin=i&7, t4=kin&3, kh=kin>>2;
        int ot=f>>3, g=f&7;
        g_FC1F[(((kk*16+ot)<<5)+((g<<2)|t4))*2 + kh] = f2tf32(w);
    } else if (t < 6144+16384+8192+6144){           // forward-DFT B-frags
        int u = t - 6144 - 16384 - 8192;
        int kk = u/192; int r = u%192;
        int nt = r/64;  int r2 = r%64;
        int lane = r2>>1, kh = r2&1;
        int t4 = lane&3, g = lane>>2;
        int y = kk*8 + t4 + 4*kh;
        int n = nt*8 + g;
        int k = n>>1;
        int rr = (k*y) & 255;
        double s,c; sincospi(2.0*rr/256.0, &s, &c);
        float v = (n&1)? (float)(-s) : (float)c;
        g_TYBF[((kk*3+nt)*32 + lane)*2 + kh] = f2tf32(v);
    }
}

// ---------------- lift (fc0) + fused y-DFT ----------------
#define LIFT_SMEM (CH*PADH*4)
__global__ void __launch_bounds__(256) k_lift(const float* __restrict__ x,
                                              const float* __restrict__ fw,
                                              const float* __restrict__ fb){
    extern __shared__ float HS[];   // [64][PADH] tf32 tile
    __shared__ float w[CH*3];
    __shared__ float bsh[CH];
    if (threadIdx.x < CH*3) w[threadIdx.x]   = fw[threadIdx.x];
    if (threadIdx.x < CH)   bsh[threadIdx.x] = fb[threadIdx.x];
    __syncthreads();
    int b = blockIdx.x>>8, xr = blockIdx.x&255;
    int y = threadIdx.x;
    float xin = x[(((size_t)b)<<16) + (xr<<8) + y];
    float gx = xr*(1.0f/255.0f), gy = y*(1.0f/255.0f);
    for (int wo=0; wo<CH; wo++){
        float v = w[wo*3]*xin + w[wo*3+1]*gx + w[wo*3+2]*gy + bsh[wo];
        g_h[0][(((size_t)(b*CH+wo))<<16) + (xr<<8) + y] = v;
        HS[wo*PADH + y] = f2tf32(v);
    }
    __syncthreads();
    dft_epi(HS, b, xr, threadIdx.x>>5, threadIdx.x&31);
}

// ---------------- K2: DFT over x ----------------
#define DFTX_SMEM ((KXM*HH*2 + HH*MM*2)*4)
__global__ void k_dftx(){
    extern __shared__ float sm[];
    float2* tws = (float2*)sm;           // [24][256]
    float2* fcs = tws + KXM*HH;          // [256][12]
    int bc = blockIdx.x;
    const float2* src = (const float2*)(g_Fy + (size_t)bc*HH*24);
    for (int i=threadIdx.x; i<KXM*HH; i+=288) tws[i]=((const float2*)g_TX)[i];
    for (int i=threadIdx.x; i<HH*MM; i+=288)  fcs[i]=src[i];
    __syncthreads();
    int t = threadIdx.x;
    int j = t/12, ky = t%12;
    const float2* tw = tws + j*HH;
    float sr=0.f, si=0.f;
#pragma unroll 4
    for (int xx=0; xx<HH; xx++){
        float2 w = tw[xx];
        float2 v = fcs[xx*12+ky];
        sr += v.x*w.x + v.y*w.y;
        si += v.y*w.x - v.x*w.y;
    }
    size_t o = ((size_t)bc*288 + t)*2;
    g_G[o]=sr; g_G[o+1]=si;
}

// ---------------- K3: complex mode mixing ----------------
__global__ void k_modemix(const float* __restrict__ w1, const float* __restrict__ w2, int layer){
    __shared__ float gr[512], gi[512];
    __shared__ float wr[4096], wi[4096];
    int m = blockIdx.x; int j = m/12, ky = m%12;
    const float* W = (j<12)? w1 : w2;
    int jm = (j<12)? j : (j-12);
    for (int t=threadIdx.x; t<4096; t+=256){
        int i = t>>6, o = t&63;
        size_t idx = (((((size_t)layer*CH + i)*CH + o)*MM + jm)*MM + ky)*2;
        wr[t]=W[idx]; wi[t]=W[idx+1];
    }
    for (int t=threadIdx.x; t<512; t+=256){
        size_t idx = ((size_t)t*288 + m)*2;
        gr[t]=g_G[idx]; gi[t]=g_G[idx+1];
    }
    __syncthreads();
    int t = threadIdx.x;
    int o = t & 63;
#pragma unroll
    for (int bh=0; bh<2; bh++){
        int b = (t>>6) + 4*bh;
        float sr=0.f, si=0.f;
        for (int i=0;i<CH;i++){
            float a = gr[b*64+i], bb = gi[b*64+i];
            float c = wr[i*64+o], d  = wi[i*64+o];
            sr += a*c - bb*d;
            si += a*d + bb*c;
        }
        size_t idx = (((size_t)b*CH + o)*288 + m)*2;
        g_G2[idx]=sr; g_G2[idx+1]=si;
    }
}

// ---------------- K4: inverse over x ----------------
__global__ void k_invx(){
    __shared__ float jr[288], ji[288];
    int bo = blockIdx.x;
    for (int t=threadIdx.x; t<288; t+=256){
        jr[t]=g_G2[((size_t)bo*288+t)*2];
        ji[t]=g_G2[((size_t)bo*288+t)*2+1];
    }
    __syncthreads();
    int xx = threadIdx.x;
    float er[12], ei[12];
#pragma unroll
    for(int k=0;k<12;k++){ er[k]=0.f; ei[k]=0.f; }
    for (int j=0;j<KXM;j++){
        float c = g_TX[(j*HH+xx)*2], s = g_TX[(j*HH+xx)*2+1];
#pragma unroll
        for (int ky=0;ky<12;ky++){
            float a = jr[j*12+ky], b = ji[j*12+ky];
            er[ky] += a*c - b*s;
            ei[ky] += b*c + a*s;
        }
    }
    const float inv = 1.0f/65536.0f;
    float* o = g_E + (((size_t)bo)*HH + xx)*24;
#pragma unroll
    for (int ky=0;ky<12;ky++){ o[2*ky]=er[ky]*inv; o[2*ky+1]=ei[ky]*inv; }
}

// ---------------- K5: fused layer (pw conv + inv-y + bias + GELU + fwd-DFT) ----------------
#define NKK5 11
#define AF5_F (NKK5*16*32*4)     /* 22528 floats */
#define BF5_F (NKK5*8*32*2)      /* 5632 floats */
#define K5_SMEM ((AF5_F + BF5_F + 64)*4)

__global__ void __launch_bounds__(256)
k_layer(const float* __restrict__ pw_b, int layer, int src, int dogelu){
    extern __shared__ float sm[];
    float* AF = sm;
    float* BF = AF + AF5_F;
    float* bs = BF + BF5_F;
    float* HS = sm;                  // overlays AF after main loop
    int b = blockIdx.x >> 8, xr = blockIdx.x & 255;
    const float* hin = g_h[src];
    float* hout = g_h[src^1];
    int tid = threadIdx.x;

    for (int t=tid; t<CH*64; t+=256){
        int i=t>>6, q=t&63;
        float4 v = ((const float4*)(hin + (((size_t)(b*CH+i))<<16) + (xr<<8)))[q];
        int kk=i>>3, kin=i&7, t4=kin&3, kh=kin>>2;
        float vv[4] = {v.x, v.y, v.z, v.w};
#pragma unroll
        for (int d=0; d<4; d++){
            int y = q*4+d; int yt=y>>4, yin=y&15, g=yin&7, half=yin>>3;
            AF[(((kk*16+yt)<<5)+((g<<2)|t4))*4 + ((kh<<1)|half)] = f2tf32(vv[d]);
        }
    }
    for (int t=tid; t<1536; t+=256)
        ((float4*)AF)[4096 + t] = ((const float4*)g_TYF)[t];
    for (int t=tid; t<1024; t+=256)
        ((float4*)BF)[t] = ((const float4*)(g_PWF + layer*4096))[t];
    for (int t=tid; t<KXM*CH; t+=256){
        int o = t/24, ke = t%24;
        float v = g_E[(((size_t)(b*CH+o))*HH + xr)*24 + ke];
        int kk=8+(ke>>3), kin=ke&7, t4=kin&3, kh=kin>>2;
        int ot=o>>3, g=o&7;
        BF[(((kk*8+ot)<<5)+((g<<2)|t4))*2 + kh] = f2tf32(v);
    }
    if (tid<CH) bs[tid]=pw_b[layer*CH+tid];
    __syncthreads();

    int lane = tid & 31, warp = tid >> 5;
    int wy = warp >> 1, wo = warp & 1;        // 4 x 2 warp grid, tile 64y x 32o

    float c[4][4][4];
#pragma unroll
    for (int mi=0;mi<4;mi++)
#pragma unroll
        for (int ni=0;ni<4;ni++)
#pragma unroll
            for (int r=0;r<4;r++) c[mi][ni][r]=0.f;

    for (int kk=0; kk<NKK5; kk++){
        float2 bf[4];
#pragma unroll
        for (int ni=0;ni<4;ni++){
            int ot = wo*4+ni;
            bf[ni] = ((const float2*)BF)[((kk*8+ot)<<5)+lane];
        }
#pragma unroll
        for (int mi=0;mi<4;mi++){
            int yt = wy*4+mi;
            float4 af = ((const float4*)AF)[((kk*16+yt)<<5)+lane];
#pragma unroll
            for (int ni=0;ni<4;ni++){
                mma_tf32(c[mi][ni][0],c[mi][ni][1],c[mi][ni][2],c[mi][ni][3],
                         af.x,af.y,af.z,af.w, bf[ni].x, bf[ni].y);
            }
        }
    }

    int g = lane>>2, t4 = lane&3;
    float vbuf[4][4][4];
#pragma unroll
    for (int mi=0;mi<4;mi++){
#pragma unroll
        for (int ni=0;ni<4;ni++){
            int o = (wo*4+ni)*8 + 2*t4;
            float bb0 = bs[o], bb1 = bs[o+1];
            float v0 = c[mi][ni][0] + bb0;
            float v1 = c[mi][ni][1] + bb1;
            float v2 = c[mi][ni][2] + bb0;
            float v3 = c[mi][ni][3] + bb1;
            if (dogelu){ v0=gelu_f(v0); v1=gelu_f(v1); v2=gelu_f(v2); v3=gelu_f(v3); }
            vbuf[mi][ni][0]=v0; vbuf[mi][ni][1]=v1; vbuf[mi][ni][2]=v2; vbuf[mi][ni][3]=v3;
        }
    }
    // global writes (do NOT touch smem yet — AF still live until sync)
#pragma unroll
    for (int mi=0;mi<4;mi++){
        int y = (wy*4+mi)*16 + g;
#pragma unroll
        for (int ni=0;ni<4;ni++){
            int o = (wo*4+ni)*8 + 2*t4;
            float* p0 = hout + (((size_t)(b*CH+o  ))<<16) + (xr<<8);
            float* p1 = hout + (((size_t)(b*CH+o+1))<<16) + (xr<<8);
            p0[y]   = vbuf[mi][ni][0];
            p1[y]   = vbuf[mi][ni][1];
            p0[y+8] = vbuf[mi][ni][2];
            p1[y+8] = vbuf[mi][ni][3];
        }
    }
    if (!dogelu) return;     // last layer: no forward DFT needed

    __syncthreads();         // retire AF reads before HS overlay
#pragma unroll
    for (int mi=0;mi<4;mi++){
        int y = (wy*4+mi)*16 + g;
#pragma unroll
        for (int ni=0;ni<4;ni++){
            int o = (wo*4+ni)*8 + 2*t4;
            HS[ o   *PADH + y  ] = f2tf32(vbuf[mi][ni][0]);
            HS[(o+1)*PADH + y  ] = f2tf32(vbuf[mi][ni][1]);
            HS[ o   *PADH + y+8] = f2tf32(vbuf[mi][ni][2]);
            HS[(o+1)*PADH + y+8] = f2tf32(vbuf[mi][ni][3]);
        }
    }
    __syncthreads();
    dft_epi(HS, b, xr, warp, lane);
}

// ---------------- K6: fused head ----------------
#define NKK6 8
#define AF6_F (NKK6*16*32*4)
#define BF6_F (NKK6*16*32*2)
#define K6_SMEM ((AF6_F + BF6_F + 2*WW + 2*FCH)*4)

__global__ void __launch_bounds__(256)
k_head(const float* __restrict__ fc1b, const float* __restrict__ fc2w,
       const float* __restrict__ fc2b, float* __restrict__ out, int src){
    extern __shared__ float sm[];
    float* AF   = sm;
    float* BF   = AF + AF6_F;
    float* part = BF + BF6_F;
    float* b1s  = part + 2*WW;
    float* w2s  = b1s + FCH;
    int b = blockIdx.x>>8, xr = blockIdx.x&255;
    const float* hin = g_h[src];
    int tid = threadIdx.x;

    for (int t=tid; t<CH*64; t+=256){
        int i=t>>6, q=t&63;
        float4 v = ((const float4*)(hin + (((size_t)(b*CH+i))<<16) + (xr<<8)))[q];
        int kk=i>>3, kin=i&7, t4=kin&3, kh=kin>>2;
        float vv[4] = {v.x, v.y, v.z, v.w};
#pragma unroll
        for (int d=0; d<4; d++){
            int y = q*4+d; int yt=y>>4, yin=y&15, g=yin&7, half=yin>>3;
            AF[(((kk*16+yt)<<5)+((g<<2)|t4))*4 + ((kh<<1)|half)] = f2tf32(vv[d]);
        }
    }
    for (int t=tid; t<2048; t+=256)
        ((float4*)BF)[t] = ((const float4*)g_FC1F)[t];
    if (tid<FCH){ b1s[tid]=fc1b[tid]; w2s[tid]=fc2w[tid]; }
    __syncthreads();

    int lane = tid & 31, warp = tid >> 5;
    int wy = warp >> 1, wf = warp & 1;

    float c[4][8][4];
#pragma unroll
    for (int mi=0;mi<4;mi++)
#pragma unroll
        for (int ni=0;ni<8;ni++)
#pragma unroll
            for (int r=0;r<4;r++) c[mi][ni][r]=0.f;

    for (int kk=0; kk<NKK6; kk++){
        float2 bf[8];
#pragma unroll
        for (int ni=0;ni<8;ni++){
            int ot = wf*8+ni;
            bf[ni] = ((const float2*)BF)[((kk*16+ot)<<5)+lane];
        }
#pragma unroll
        for (int mi=0;mi<4;mi++){
            int yt = wy*4+mi;
            float4 af = ((const float4*)AF)[((kk*16+yt)<<5)+lane];
#pragma unroll
            for (int ni=0;ni<8;ni++){
                mma_tf32(c[mi][ni][0],c[mi][ni][1],c[mi][ni][2],c[mi][ni][3],
                         af.x,af.y,af.z,af.w, bf[ni].x, bf[ni].y);
            }
        }
    }

    int g = lane>>2, t4 = lane&3;
#pragma unroll
    for (int mi=0;mi<4;mi++){
        float s0=0.f, s1=0.f;
#pragma unroll
        for (int ni=0;ni<8;ni++){
            int f = (wf*8+ni)*8 + 2*t4;
            float ba = b1s[f], bb = b1s[f+1];
            float wa = w2s[f], wb = w2s[f+1];
            s0 += gelu_f(c[mi][ni][0]+ba)*wa + gelu_f(c[mi][ni][1]+bb)*wb;
            s1 += gelu_f(c[mi][ni][2]+ba)*wa + gelu_f(c[mi][ni][3]+bb)*wb;
        }
        s0 += __shfl_xor_sync(0xffffffffu, s0, 1);
        s0 += __shfl_xor_sync(0xffffffffu, s0, 2);
        s1 += __shfl_xor_sync(0xffffffffu, s1, 1);
        s1 += __shfl_xor_sync(0xffffffffu, s1, 2);
        if (t4==0){
            int y = (wy*4+mi)*16 + g;
            part[wf*WW + y]   = s0;
            part[wf*WW + y+8] = s1;
        }
    }
    __syncthreads();
    {
        int y = tid;
        float s = part[y] + part[WW+y] + fc2b[0];
        out[(((size_t)b)<<16) + (xr<<8) + y] = s;
    }
}

// ---------------- launch ----------------
extern "C" void kernel_launch(void* const* d_in, const int* in_sizes, int n_in,
                              void* d_out, int out_size){
    (void)in_sizes; (void)n_in; (void)out_size;
    const float* x     = (const float*)d_in[0];
    const float* fc0_w = (const float*)d_in[1];
    const float* fc0_b = (const float*)d_in[2];
    const float* w1    = (const float*)d_in[3];
    const float* w2    = (const float*)d_in[4];
    const float* pw_w  = (const float*)d_in[5];
    const float* pw_b  = (const float*)d_in[6];
    const float* fc1_w = (const float*)d_in[7];
    const float* fc1_b = (const float*)d_in[8];
    const float* fc2_w = (const float*)d_in[9];
    const float* fc2_b = (const float*)d_in[10];
    float* out = (float*)d_out;

    cudaFuncSetAttribute(k_layer, cudaFuncAttributeMaxDynamicSharedMemorySize, K5_SMEM);
    cudaFuncSetAttribute(k_head,  cudaFuncAttributeMaxDynamicSharedMemorySize, K6_SMEM);
    cudaFuncSetAttribute(k_dftx,  cudaFuncAttributeMaxDynamicSharedMemorySize, DFTX_SMEM);
    cudaFuncSetAttribute(k_lift,  cudaFuncAttributeMaxDynamicSharedMemorySize, LIFT_SMEM);

    k_tables<<<24,256>>>();
    k_frw<<<144,256>>>(pw_w, fc1_w);
    k_lift<<<BATCH*HH,256,LIFT_SMEM>>>(x, fc0_w, fc0_b);
    for (int l=0; l<NLAYERS; l++){
        int src = l & 1;
        k_dftx<<<BATCH*CH,288,DFTX_SMEM>>>();
        k_modemix<<<KXM*MM,256>>>(w1, w2, l);
        k_invx<<<BATCH*CH,256>>>();
        k_layer<<<BATCH*HH,256,K5_SMEM>>>(pw_b, l, src, (l<NLAYERS-1)?1:0);
    }
    k_head<<<BATCH*HH,256,K6_SMEM>>>(fc1_b, fc2_w, fc2_b, out, 0);
}

// round 5
// speedup vs baseline: 1.9891x; 1.2371x over previous
#include <cuda_runtime.h>
#include <cstdint>
#include <cstddef>

#define BATCH 8
#define CH 64
#define HH 256
#define WW 256
#define MM 12
#define KXM 24
#define NLAYERS 4
#define FCH 128
#define HW (HH*WW)
#define BCHW (BATCH*CH*HW)
#define PADH 260

// ---------------- device scratch ----------------
__device__ float g_h[BCHW];                    // single-buffer activations [b,c,x,y]
__device__ float g_Fy[BATCH*MM*CH*HH*2];       // [b][ky][c][x] float2
__device__ float g_E [BATCH*HH*CH*KXM];        // [b][x][o][ke], ke=2ky+ri
__device__ float g_TYinv[KXM*HH];              // inverse-y real basis [k][y]
// pre-fragmented constant operands (tf32)
__device__ float g_TYF[3*16*32*4];             // A-frags TYinv (k_layer kk 8..10)
__device__ float g_PWF[NLAYERS*8*8*32*2];      // B-frags pw weights per layer
__device__ float g_FC1F[8*16*32*2];            // B-frags fc1 weights
__device__ float g_TYBF[32*3*32*2];            // B-frags forward y-DFT basis
__device__ float g_F1A[64*3*32*4];             // A-frags fwd x-DFT (M=48,K=512)
__device__ float g_F2B[6*64*32*2];             // B-frags inv x-DFT (K=48,N=512), /65536
__device__ float g_WMIX[NLAYERS*MM*KXM*CH*CH*2]; // [l][ky][j][i][o] float2

__device__ __forceinline__ float gelu_f(float v){
    return 0.5f*v*(1.0f + erff(v*0.70710678118654752f));
}
__device__ __forceinline__ float f2tf32(float x){
    uint32_t r; asm("cvt.rna.tf32.f32 %0, %1;" : "=r"(r) : "f"(x));
    return __uint_as_float(r);
}
__device__ __forceinline__ void mma_tf32(float& d0,float& d1,float& d2,float& d3,
                                         float a0,float a1,float a2,float a3,
                                         float b0,float b1){
    asm volatile("mma.sync.aligned.m16n8k8.row.col.f32.tf32.tf32.f32 "
        "{%0,%1,%2,%3}, {%4,%5,%6,%7}, {%8,%9}, {%0,%1,%2,%3};"
        : "+f"(d0),"+f"(d1),"+f"(d2),"+f"(d3)
        : "r"(__float_as_uint(a0)),"r"(__float_as_uint(a1)),
          "r"(__float_as_uint(a2)),"r"(__float_as_uint(a3)),
          "r"(__float_as_uint(b0)),"r"(__float_as_uint(b1)));
}

// ---------------- fused y-DFT epilogue: Fy[b][ky][o][x] ----------------
__device__ __forceinline__ void dft_epi(const float* __restrict__ HS, int b, int xr,
                                        int warp, int lane){
    if (warp >= 4) return;
    int g = lane>>2, t4 = lane&3;
    int mt = warp;
    float c[3][4];
#pragma unroll
    for (int nt=0;nt<3;nt++)
#pragma unroll
        for (int r=0;r<4;r++) c[nt][r]=0.f;
    const float2* TB = (const float2*)g_TYBF;
    for (int kk=0; kk<32; kk++){
        float a0 = HS[(mt*16+g  )*PADH + kk*8+t4];
        float a1 = HS[(mt*16+g+8)*PADH + kk*8+t4];
        float a2 = HS[(mt*16+g  )*PADH + kk*8+t4+4];
        float a3 = HS[(mt*16+g+8)*PADH + kk*8+t4+4];
#pragma unroll
        for (int nt=0;nt<3;nt++){
            float2 bf = __ldg(TB + (kk*3+nt)*32 + lane);
            mma_tf32(c[nt][0],c[nt][1],c[nt][2],c[nt][3], a0,a1,a2,a3, bf.x,bf.y);
        }
    }
    float2* Fy2 = (float2*)g_Fy;
    int o = mt*16+g;
#pragma unroll
    for (int nt=0;nt<3;nt++){
        int ky = nt*4+t4;
        size_t base = (((size_t)(b*MM+ky)*CH + o)<<8) + xr;
        Fy2[base]         = make_float2(c[nt][0], c[nt][1]);
        Fy2[base + (8<<8)] = make_float2(c[nt][2], c[nt][3]);   // o+8
    }
}

// ---------------- TYinv table ----------------
__global__ void k_tables(){
    int t = blockIdx.x*blockDim.x + threadIdx.x;
    if (t < KXM*HH){
        int kk = t/HH, y = t%HH;
        int ky2 = kk>>1;
        int r2 = (ky2*y) & 255;
        double s2,c2; sincospi(2.0*r2/256.0, &s2, &c2);
        float v;
        if ((kk&1)==0) v = (ky2==0)? 1.0f : 2.0f*(float)c2;
        else           v = (ky2==0)? 0.0f : -2.0f*(float)s2;
        g_TYinv[t] = v;
    }
}

// ---------------- fragment pre-pack ----------------
__global__ void k_frw(const float* __restrict__ pw_w, const float* __restrict__ fc1w){
    int t = blockIdx.x*blockDim.x + threadIdx.x;
    if (t < 6144){                                  // TYinv A-frags
        int k = t>>8, y = t&255;
        float v = g_TYinv[k*256 + y];
        int kk=k>>3, kin=k&7, t4=kin&3, kh=kin>>2;
        int yt=y>>4, yin=y&15, g=yin&7, half=yin>>3;
        g_TYF[(((kk*16+yt)<<5) + ((g<<2)|t4))*4 + ((kh<<1)|half)] = f2tf32(v);
    } else if (t < 22528){                          // pw B-frags
        int u = t - 6144;
        int layer = u>>12; int v = u&4095;
        int k = v&63, o = v>>6;
        float w = pw_w[(layer*CH+o)*CH + k];
        int kk=k>>3, kin=k&7, t4=kin&3, kh=kin>>2;
        int ot=o>>3, g=o&7;
        g_PWF[layer*4096 + (((kk*8+ot)<<5)+((g<<2)|t4))*2 + kh] = f2tf32(w);
    } else if (t < 30720){                          // fc1 B-frags
        int u = t - 22528;
        int i = u&63, f = u>>6;
        float w = fc1w[f*CH + i];
        int kk=i>>3, kin=i&7, t4=kin&3, kh=kin>>2;
        int ot=f>>3, g=f&7;
        g_FC1F[(((kk*16+ot)<<5)+((g<<2)|t4))*2 + kh] = f2tf32(w);
    } else if (t < 36864){                          // forward-DFT (y) B-frags
        int u = t - 30720;
        int kk = u/192; int r = u%192;
        int nt = r/64;  int r2 = r%64;
        int lane = r2>>1, kh = r2&1;
        int t4 = lane&3, g = lane>>2;
        int y = kk*8 + t4 + 4*kh;
        int n = nt*8 + g;
        int k = n>>1;
        int rr = (k*y) & 255;
        double s,c; sincospi(2.0*rr/256.0, &s, &c);
        float v = (n&1)? (float)(-s) : (float)c;
        g_TYBF[((kk*3+nt)*32 + lane)*2 + kh] = f2tf32(v);
    } else if (t < 61440){                          // fwd x-DFT A-frags (M=48,K=512)
        int u = t - 36864;
        int slot = u&3, lane = (u>>2)&31, mt = (u>>7)%3, kk = u/384;
        int g = lane>>2, t4 = lane&3, half = slot&1, kh = slot>>1;
        int m = mt*16 + g + 8*half;
        int k = kk*8 + t4 + 4*kh;
        int j = m>>1, ri = m&1;
        int x = k>>1, xi = k&1;
        int keff = (j<12)? j : (j-24);
        int rr = ((keff*x)%256 + 256) & 255;
        double s,c; sincospi(2.0*rr/256.0, &s, &c);
        float v = (ri==0) ? ((xi==0)? (float)c : (float)s)
                          : ((xi==0)? (float)(-s) : (float)c);
        g_F1A[u] = f2tf32(v);
    } else if (t < 86016){                          // inv x-DFT B-frags (K=48,N=512)
        int u = t - 61440;
        int kh = u&1, lane = (u>>1)&31, nt = (u>>6)&63, kk = u>>12;
        int g = lane>>2, t4 = lane&3;
        int k = kk*8 + t4 + 4*kh;
        int j = k>>1, ri = k&1;
        int n = nt*8 + g;
        int x = n>>1, xi = n&1;
        int keff = (j<12)? j : (j-24);
        int rr = ((keff*x)%256 + 256) & 255;
        double s,c; sincospi(2.0*rr/256.0, &s, &c);
        float v = (ri==0) ? ((xi==0)? (float)c : (float)s)
                          : ((xi==0)? (float)(-s) : (float)c);
        g_F2B[u] = f2tf32(v * (1.0f/65536.0f));
    }
}

// ---------------- weight transpose for mix: [l][ky][j][i][o] ----------------
__global__ void k_wmix(const float* __restrict__ w1, const float* __restrict__ w2){
    int t = blockIdx.x*blockDim.x + threadIdx.x;
    if (t >= NLAYERS*CH*CH*MM*MM) return;
    // t = ((((layer*64+i)*64+o)*12+jm)*12+ky)  — matches source linear layout
    int ky = t%12;
    int jm = (t/12)%12;
    int o  = (t/144)&63;
    int i  = (t/9216)&63;
    int layer = t/589824;
    float2 v1 = ((const float2*)w1)[t];
    float2 v2 = ((const float2*)w2)[t];
    float2* dst = (float2*)g_WMIX;
    size_t b0 = ((size_t)(layer*12+ky)*24);
    dst[(b0 + jm   )*4096 + i*64 + o] = v1;
    dst[(b0 + jm+12)*4096 + i*64 + o] = v2;
}

// ---------------- lift (fc0) + fused y-DFT ----------------
#define LIFT_SMEM (CH*PADH*4)
__global__ void __launch_bounds__(256) k_lift(const float* __restrict__ x,
                                              const float* __restrict__ fw,
                                              const float* __restrict__ fb){
    extern __shared__ float HS[];   // [64][PADH]
    __shared__ float w[CH*3];
    __shared__ float bsh[CH];
    if (threadIdx.x < CH*3) w[threadIdx.x]   = fw[threadIdx.x];
    if (threadIdx.x < CH)   bsh[threadIdx.x] = fb[threadIdx.x];
    __syncthreads();
    int b = blockIdx.x>>8, xr = blockIdx.x&255;
    int y = threadIdx.x;
    float xin = x[(((size_t)b)<<16) + (xr<<8) + y];
    float gx = xr*(1.0f/255.0f), gy = y*(1.0f/255.0f);
    for (int wo=0; wo<CH; wo++){
        float v = w[wo*3]*xin + w[wo*3+1]*gx + w[wo*3+2]*gy + bsh[wo];
        g_h[(((size_t)(b*CH+wo))<<16) + (xr<<8) + y] = v;
        HS[wo*PADH + y] = f2tf32(v);
    }
    __syncthreads();
    dft_epi(HS, b, xr, threadIdx.x>>5, threadIdx.x&31);
}

// ---------------- K-spec: fused (x-DFT -> mode mix -> x-inverse) per (b,ky) ----------------
#define BF1_F2 (64*8*32)                 /* 16384 float2 */
#define G_STRIDE 65
#define G_F (48*G_STRIDE)                /* 3120 floats */
#define AF2_F (6*4*32*4)                 /* 3072 floats */
#define SPEC_SMEM ((BF1_F2*2 + G_F + AF2_F)*4)

__global__ void __launch_bounds__(512,1)
k_spec(int layer){
    extern __shared__ float sm[];
    float* BF1f = sm;                    // B-frags of Fy, 32768 floats
    float* Gs   = sm + 2*BF1_F2;         // [48][65]
    float* AF2  = Gs + G_F;              // A-frags of G2
    int b = blockIdx.x/12, ky = blockIdx.x%12;
    int tid = threadIdx.x, lane = tid&31, warp = tid>>5;

    // pack Fy tile -> B-frags (k = 2x+ri, n = c)
    const float2* fy = ((const float2*)g_Fy) + (((size_t)(b*MM+ky))<<14);
    for (int t=tid; t<64*256; t+=512){
        int c = t>>8, x = t&255;
        float2 v = fy[t];
        int nt=c>>3, g=c&7;
        int k0=2*x;
        int kk=k0>>3, t4=k0&3, kh=(k0>>2)&1;
        int base = ((kk*8+nt)<<5);
        BF1f[(base + ((g<<2)|t4    ))*2 + kh] = f2tf32(v.x);
        BF1f[(base + ((g<<2)|(t4+1)))*2 + kh] = f2tf32(v.y);
    }
    __syncthreads();

    // GEMM1: G[m=2j+ri][c] = A(twiddle, global frags) x BF1
    {
        const float4* A4 = (const float4*)g_F1A;
        const float2* B2 = (const float2*)BF1f;
        for (int T=warp; T<24; T+=16){
            int mt = T%3, nt = T/3;
            float c0=0.f,c1=0.f,c2=0.f,c3=0.f;
#pragma unroll 8
            for (int kk=0; kk<64; kk++){
                float4 a = __ldg(A4 + ((kk*3+mt)<<5)+lane);
                float2 bf = B2[((kk*8+nt)<<5)+lane];
                mma_tf32(c0,c1,c2,c3, a.x,a.y,a.z,a.w, bf.x,bf.y);
            }
            int g=lane>>2, t4=lane&3;
            int row = mt*16+g, col = nt*8+2*t4;
            Gs[row*G_STRIDE+col]       = c0;
            Gs[row*G_STRIDE+col+1]     = c1;
            Gs[(row+8)*G_STRIDE+col]   = c2;
            Gs[(row+8)*G_STRIDE+col+1] = c3;
        }
    }
    __syncthreads();

    // mix: G2[o][j] = sum_i G[i][j] * W[i][o]  (fp32 scalar), write A-frags
    {
        const float2* WM = ((const float2*)g_WMIX) + ((size_t)((layer*12+ky)*24))*4096;
#pragma unroll
        for (int r=0; r<3; r++){
            int item = tid + 512*r;
            int j = item>>6, o = item&63;
            const float2* wrow = WM + j*4096 + o;
            const float* Gr = Gs + (2*j)*G_STRIDE;
            const float* Gi = Gs + (2*j+1)*G_STRIDE;
            float ar=0.f, ai=0.f;
#pragma unroll 8
            for (int i=0;i<64;i++){
                float2 wv = __ldg(wrow + i*64);
                float gr = Gr[i], gi = Gi[i];
                ar += gr*wv.x - gi*wv.y;
                ai += gr*wv.y + gi*wv.x;
            }
            int mt=o>>4, half=(o>>3)&1, gg=o&7;
            int k0=2*j;
            int kk=k0>>3, t40=k0&3, kh=(k0>>2)&1;
            int base = ((kk*4+mt)<<5);
            AF2[(base + ((gg<<2)|t40    ))*4 + ((kh<<1)|half)] = f2tf32(ar);
            AF2[(base + ((gg<<2)|(t40+1)))*4 + ((kh<<1)|half)] = f2tf32(ai);
        }
    }
    __syncthreads();

    // GEMM2: E[o][n=2x+ri] = AF2 x B(inv twiddle, global frags)
    {
        int mt = warp&3, ntb = (warp>>2)<<4;
        float4 Areg[6];
#pragma unroll
        for (int kk=0;kk<6;kk++)
            Areg[kk] = ((const float4*)AF2)[((kk*4+mt)<<5)+lane];
        int g=lane>>2, t4=lane&3;
        const float2* B2 = (const float2*)g_F2B;
        float2* E2 = (float2*)g_E;
        for (int ni=0;ni<16;ni++){
            int nt = ntb+ni;
            float c0=0.f,c1=0.f,c2=0.f,c3=0.f;
#pragma unroll
            for (int kk=0;kk<6;kk++){
                float2 bf = __ldg(B2 + ((kk*64+nt)<<5)+lane);
                mma_tf32(c0,c1,c2,c3, Areg[kk].x,Areg[kk].y,Areg[kk].z,Areg[kk].w,
                         bf.x,bf.y);
            }
            int x = nt*4+t4, o = mt*16+g;
            E2[((size_t)(b*HH+x)*CH + o  )*12 + ky] = make_float2(c0,c1);
            E2[((size_t)(b*HH+x)*CH + o+8)*12 + ky] = make_float2(c2,c3);
        }
    }
}

// ---------------- K5: fused layer (pw conv + inv-y + bias + GELU + fwd y-DFT) ----------------
// smem: region0 = 16640 floats (AF h-frags 16384 / HS overlay 16640), EF 1536, bias 64
#define K5_SMEM ((16640 + 1536 + 64)*4)

__global__ void __launch_bounds__(256,2)
k_layer(const float* __restrict__ pw_b, int layer, int dogelu){
    extern __shared__ float sm[];
    float* AF = sm;                  // h A-frags, kk 0..7 (16384 floats)
    float* HS = sm;                  // overlay [64][PADH]
    float* EF = sm + 16640;          // E B-frags, kk 0..2 (1536)
    float* bs = EF + 1536;
    int b = blockIdx.x >> 8, xr = blockIdx.x & 255;
    int tid = threadIdx.x;

    for (int t=tid; t<CH*64; t+=256){
        int i=t>>6, q=t&63;
        float4 v = ((const float4*)(g_h + (((size_t)(b*CH+i))<<16) + (xr<<8)))[q];
        int kk=i>>3, kin=i&7, t4=kin&3, kh=kin>>2;
        float vv[4] = {v.x, v.y, v.z, v.w};
#pragma unroll
        for (int d=0; d<4; d++){
            int y = q*4+d; int yt=y>>4, yin=y&15, g=yin&7, half=yin>>3;
            AF[(((kk*16+yt)<<5)+((g<<2)|t4))*4 + ((kh<<1)|half)] = f2tf32(vv[d]);
        }
    }
    {   // E (coalesced) -> B-frags
        const float* Eb = g_E + ((size_t)(b*HH+xr))*CH*24;
        for (int t=tid; t<KXM*CH; t+=256){
            float v = Eb[t];
            int o = t/24, ke = t%24;
            int kk=ke>>3, t4=ke&3, kh=(ke>>2)&1;
            int ot=o>>3, g=o&7;
            EF[(((kk*8+ot)<<5)+((g<<2)|t4))*2 + kh] = f2tf32(v);
        }
    }
    if (tid<CH) bs[tid]=pw_b[layer*CH+tid];
    __syncthreads();

    int lane = tid & 31, warp = tid >> 5;
    int wy = warp >> 1, wo = warp & 1;        // 4 x 2 warp grid, 64y x 32o

    float c[4][4][4];
#pragma unroll
    for (int mi=0;mi<4;mi++)
#pragma unroll
        for (int ni=0;ni<4;ni++)
#pragma unroll
            for (int r=0;r<4;r++) c[mi][ni][r]=0.f;

    const float2* PW2 = ((const float2*)g_PWF) + layer*2048;
    for (int kk=0; kk<8; kk++){               // h x pw (B from global)
        float2 bf[4];
#pragma unroll
        for (int ni=0;ni<4;ni++)
            bf[ni] = __ldg(PW2 + ((kk*8 + wo*4+ni)<<5)+lane);
#pragma unroll
        for (int mi=0;mi<4;mi++){
            float4 af = ((const float4*)AF)[((kk*16 + wy*4+mi)<<5)+lane];
#pragma unroll
            for (int ni=0;ni<4;ni++)
                mma_tf32(c[mi][ni][0],c[mi][ni][1],c[mi][ni][2],c[mi][ni][3],
                         af.x,af.y,af.z,af.w, bf[ni].x, bf[ni].y);
        }
    }
    const float4* TY4 = (const float4*)g_TYF;
    for (int kk=0; kk<3; kk++){               // TYinv (A from global) x E (B from smem)
        float2 bf[4];
#pragma unroll
        for (int ni=0;ni<4;ni++)
            bf[ni] = ((const float2*)EF)[((kk*8 + wo*4+ni)<<5)+lane];
#pragma unroll
        for (int mi=0;mi<4;mi++){
            float4 af = __ldg(TY4 + ((kk*16 + wy*4+mi)<<5)+lane);
#pragma unroll
            for (int ni=0;ni<4;ni++)
                mma_tf32(c[mi][ni][0],c[mi][ni][1],c[mi][ni][2],c[mi][ni][3],
                         af.x,af.y,af.z,af.w, bf[ni].x, bf[ni].y);
        }
    }

    int g = lane>>2, t4 = lane&3;
#pragma unroll
    for (int mi=0;mi<4;mi++){
#pragma unroll
        for (int ni=0;ni<4;ni++){
            int o = (wo*4+ni)*8 + 2*t4;
            float bb0 = bs[o], bb1 = bs[o+1];
            float v0 = c[mi][ni][0] + bb0;
            float v1 = c[mi][ni][1] + bb1;
            float v2 = c[mi][ni][2] + bb0;
            float v3 = c[mi][ni][3] + bb1;
            if (dogelu){ v0=gelu_f(v0); v1=gelu_f(v1); v2=gelu_f(v2); v3=gelu_f(v3); }
            c[mi][ni][0]=v0; c[mi][ni][1]=v1; c[mi][ni][2]=v2; c[mi][ni][3]=v3;
        }
    }
    // in-place global writes (block-private row)
#pragma unroll
    for (int mi=0;mi<4;mi++){
        int y = (wy*4+mi)*16 + g;
#pragma unroll
        for (int ni=0;ni<4;ni++){
            int o = (wo*4+ni)*8 + 2*t4;
            float* p0 = g_h + (((size_t)(b*CH+o  ))<<16) + (xr<<8);
            float* p1 = g_h + (((size_t)(b*CH+o+1))<<16) + (xr<<8);
            p0[y]   = c[mi][ni][0];
            p1[y]   = c[mi][ni][1];
            p0[y+8] = c[mi][ni][2];
            p1[y+8] = c[mi][ni][3];
        }
    }
    if (!dogelu) return;

    __syncthreads();
#pragma unroll
    for (int mi=0;mi<4;mi++){
        int y = (wy*4+mi)*16 + g;
#pragma unroll
        for (int ni=0;ni<4;ni++){
            int o = (wo*4+ni)*8 + 2*t4;
            HS[ o   *PADH + y  ] = f2tf32(c[mi][ni][0]);
            HS[(o+1)*PADH + y  ] = f2tf32(c[mi][ni][1]);
            HS[ o   *PADH + y+8] = f2tf32(c[mi][ni][2]);
            HS[(o+1)*PADH + y+8] = f2tf32(c[mi][ni][3]);
        }
    }
    __syncthreads();
    dft_epi(HS, b, xr, warp, lane);
}

// ---------------- K6: fused head (fc1 -> gelu -> fc2), 512 threads ----------------
#define K6_SMEM ((16384 + 4*WW + 2*FCH)*4)

__global__ void __launch_bounds__(512,1)
k_head(const float* __restrict__ fc1b, const float* __restrict__ fc2w,
       const float* __restrict__ fc2b, float* __restrict__ out){
    extern __shared__ float sm[];
    float* AF   = sm;                    // 16384
    float* part = sm + 16384;            // [4][256]
    float* b1s  = part + 4*WW;           // [128]
    float* w2s  = b1s + FCH;             // [128]
    int b = blockIdx.x>>8, xr = blockIdx.x&255;
    int tid = threadIdx.x;

    for (int t=tid; t<CH*64; t+=512){
        int i=t>>6, q=t&63;
        float4 v = ((const float4*)(g_h + (((size_t)(b*CH+i))<<16) + (xr<<8)))[q];
        int kk=i>>3, kin=i&7, t4=kin&3, kh=kin>>2;
        float vv[4] = {v.x, v.y, v.z, v.w};
#pragma unroll
        for (int d=0; d<4; d++){
            int y = q*4+d; int yt=y>>4, yin=y&15, g=yin&7, half=yin>>3;
            AF[(((kk*16+yt)<<5)+((g<<2)|t4))*4 + ((kh<<1)|half)] = f2tf32(vv[d]);
        }
    }
    if (tid<FCH){ b1s[tid]=fc1b[tid]; w2s[tid]=fc2w[tid]; }
    __syncthreads();

    int lane = tid & 31, warp = tid >> 5;
    int wy = warp >> 2, wf = warp & 3;        // 4 x 4 warp grid, 64y x 32f

    float c[4][4][4];
#pragma unroll
    for (int mi=0;mi<4;mi++)
#pragma unroll
        for (int ni=0;ni<4;ni++)
#pragma unroll
            for (int r=0;r<4;r++) c[mi][ni][r]=0.f;

    const float2* F2 = (const float2*)g_FC1F;
    for (int kk=0; kk<8; kk++){
        float2 bf[4];
#pragma unroll
        for (int ni=0;ni<4;ni++)
            bf[ni] = __ldg(F2 + ((kk*16 + wf*4+ni)<<5)+lane);
#pragma unroll
        for (int mi=0;mi<4;mi++){
            float4 af = ((const float4*)AF)[((kk*16 + wy*4+mi)<<5)+lane];
#pragma unroll
            for (int ni=0;ni<4;ni++)
                mma_tf32(c[mi][ni][0],c[mi][ni][1],c[mi][ni][2],c[mi][ni][3],
                         af.x,af.y,af.z,af.w, bf[ni].x, bf[ni].y);
        }
    }

    int g = lane>>2, t4 = lane&3;
#pragma unroll
    for (int mi=0;mi<4;mi++){
        float s0=0.f, s1=0.f;
#pragma unroll
        for (int ni=0;ni<4;ni++){
            int f = (wf*4+ni)*8 + 2*t4;
            float ba = b1s[f], bb = b1s[f+1];
            float wa = w2s[f], wb = w2s[f+1];
            s0 += gelu_f(c[mi][ni][0]+ba)*wa + gelu_f(c[mi][ni][1]+bb)*wb;
            s1 += gelu_f(c[mi][ni][2]+ba)*wa + gelu_f(c[mi][ni][3]+bb)*wb;
        }
        s0 += __shfl_xor_sync(0xffffffffu, s0, 1);
        s0 += __shfl_xor_sync(0xffffffffu, s0, 2);
        s1 += __shfl_xor_sync(0xffffffffu, s1, 1);
        s1 += __shfl_xor_sync(0xffffffffu, s1, 2);
        if (t4==0){
            int y = (wy*4+mi)*16 + g;
            part[wf*WW + y]   = s0;
            part[wf*WW + y+8] = s1;
        }
    }
    __syncthreads();
    if (tid < WW){
        int y = tid;
        float s = part[y] + part[WW+y] + part[2*WW+y] + part[3*WW+y] + fc2b[0];
        out[(((size_t)b)<<16) + (xr<<8) + y] = s;
    }
}

// ---------------- launch ----------------
extern "C" void kernel_launch(void* const* d_in, const int* in_sizes, int n_in,
                              void* d_out, int out_size){
    (void)in_sizes; (void)n_in; (void)out_size;
    const float* x     = (const float*)d_in[0];
    const float* fc0_w = (const float*)d_in[1];
    const float* fc0_b = (const float*)d_in[2];
    const float* w1    = (const float*)d_in[3];
    const float* w2    = (const float*)d_in[4];
    const float* pw_w  = (const float*)d_in[5];
    const float* pw_b  = (const float*)d_in[6];
    const float* fc1_w = (const float*)d_in[7];
    const float* fc1_b = (const float*)d_in[8];
    const float* fc2_w = (const float*)d_in[9];
    const float* fc2_b = (const float*)d_in[10];
    float* out = (float*)d_out;

    cudaFuncSetAttribute(k_layer, cudaFuncAttributeMaxDynamicSharedMemorySize, K5_SMEM);
    cudaFuncSetAttribute(k_head,  cudaFuncAttributeMaxDynamicSharedMemorySize, K6_SMEM);
    cudaFuncSetAttribute(k_spec,  cudaFuncAttributeMaxDynamicSharedMemorySize, SPEC_SMEM);
    cudaFuncSetAttribute(k_lift,  cudaFuncAttributeMaxDynamicSharedMemorySize, LIFT_SMEM);

    k_tables<<<24,256>>>();
    k_frw<<<336,256>>>(pw_w, fc1_w);
    k_wmix<<<18432,256>>>(w1, w2);
    k_lift<<<BATCH*HH,256,LIFT_SMEM>>>(x, fc0_w, fc0_b);
    for (int l=0; l<NLAYERS; l++){
        k_spec<<<BATCH*MM,512,SPEC_SMEM>>>(l);
        k_layer<<<BATCH*HH,256,K5_SMEM>>>(pw_b, l, (l<NLAYERS-1)?1:0);
    }
    k_head<<<BATCH*HH,512,K6_SMEM>>>(fc1_b, fc2_w, fc2_b, out);
}

// round 6
// speedup vs baseline: 2.1692x; 1.0905x over previous
#include <cuda_runtime.h>
#include <cstdint>
#include <cstddef>

#define BATCH 8
#define CH 64
#define HH 256
#define WW 256
#define MM 12
#define KXM 24
#define NLAYERS 4
#define FCH 128
#define HW (HH*WW)
#define BCHW (BATCH*CH*HW)
#define PADH 260

// ---------------- device scratch ----------------
__device__ float g_h[BCHW];                    // activations [b,c,x,y] (layer boundaries 0..2 only)
__device__ float g_Fy[BATCH*MM*CH*HH*2];       // [b][ky][c][x] float2
__device__ float g_E [BATCH*HH*CH*KXM];        // [b][x][o][ke], ke=2ky+ri
__device__ float g_TYinv[KXM*HH];              // inverse-y real basis [k][y]
// pre-fragmented constant operands (tf32)
__device__ float g_TYF[3*16*32*4];             // A-frags TYinv (k_layer kk 8..10)
__device__ float g_PWF[NLAYERS*8*8*32*2];      // B-frags pw weights per layer
__device__ float g_FC1F[8*16*32*2];            // B-frags fc1 weights
__device__ float g_TYBF[32*3*32*2];            // B-frags forward y-DFT basis
__device__ float g_F1A[64*3*32*4];             // A-frags fwd x-DFT (M=48,K=512)
__device__ float g_F2B[6*64*32*2];             // B-frags inv x-DFT (K=48,N=512), /65536
__device__ float g_WMIX[NLAYERS*MM*KXM*CH*CH*2]; // [l][ky][j][i][o] float2

__device__ __forceinline__ float gelu_f(float v){
    return 0.5f*v*(1.0f + erff(v*0.70710678118654752f));
}
__device__ __forceinline__ float f2tf32(float x){
    uint32_t r; asm("cvt.rna.tf32.f32 %0, %1;" : "=r"(r) : "f"(x));
    return __uint_as_float(r);
}
__device__ __forceinline__ void mma_tf32(float& d0,float& d1,float& d2,float& d3,
                                         float a0,float a1,float a2,float a3,
                                         float b0,float b1){
    asm volatile("mma.sync.aligned.m16n8k8.row.col.f32.tf32.tf32.f32 "
        "{%0,%1,%2,%3}, {%4,%5,%6,%7}, {%8,%9}, {%0,%1,%2,%3};"
        : "+f"(d0),"+f"(d1),"+f"(d2),"+f"(d3)
        : "r"(__float_as_uint(a0)),"r"(__float_as_uint(a1)),
          "r"(__float_as_uint(a2)),"r"(__float_as_uint(a3)),
          "r"(__float_as_uint(b0)),"r"(__float_as_uint(b1)));
}

// ---------------- fused y-DFT epilogue: Fy[b][ky][o][x] ----------------
__device__ __forceinline__ void dft_epi(const float* __restrict__ HS, int b, int xr,
                                        int warp, int lane){
    if (warp >= 4) return;
    int g = lane>>2, t4 = lane&3;
    int mt = warp;
    float c[3][4];
#pragma unroll
    for (int nt=0;nt<3;nt++)
#pragma unroll
        for (int r=0;r<4;r++) c[nt][r]=0.f;
    const float2* TB = (const float2*)g_TYBF;
    for (int kk=0; kk<32; kk++){
        float a0 = HS[(mt*16+g  )*PADH + kk*8+t4];
        float a1 = HS[(mt*16+g+8)*PADH + kk*8+t4];
        float a2 = HS[(mt*16+g  )*PADH + kk*8+t4+4];
        float a3 = HS[(mt*16+g+8)*PADH + kk*8+t4+4];
#pragma unroll
        for (int nt=0;nt<3;nt++){
            float2 bf = __ldg(TB + (kk*3+nt)*32 + lane);
            mma_tf32(c[nt][0],c[nt][1],c[nt][2],c[nt][3], a0,a1,a2,a3, bf.x,bf.y);
        }
    }
    float2* Fy2 = (float2*)g_Fy;
    int o = mt*16+g;
#pragma unroll
    for (int nt=0;nt<3;nt++){
        int ky = nt*4+t4;
        size_t base = (((size_t)(b*MM+ky)*CH + o)<<8) + xr;
        Fy2[base]          = make_float2(c[nt][0], c[nt][1]);
        Fy2[base + (8<<8)] = make_float2(c[nt][2], c[nt][3]);   // o+8
    }
}

// ---------------- TYinv table ----------------
__global__ void k_tables(){
    int t = blockIdx.x*blockDim.x + threadIdx.x;
    if (t < KXM*HH){
        int kk = t/HH, y = t%HH;
        int ky2 = kk>>1;
        int r2 = (ky2*y) & 255;
        double s2,c2; sincospi(2.0*r2/256.0, &s2, &c2);
        float v;
        if ((kk&1)==0) v = (ky2==0)? 1.0f : 2.0f*(float)c2;
        else           v = (ky2==0)? 0.0f : -2.0f*(float)s2;
        g_TYinv[t] = v;
    }
}

// ---------------- fragment pre-pack ----------------
__global__ void k_frw(const float* __restrict__ pw_w, const float* __restrict__ fc1w){
    int t = blockIdx.x*blockDim.x + threadIdx.x;
    if (t < 6144){                                  // TYinv A-frags
        int k = t>>8, y = t&255;
        float v = g_TYinv[k*256 + y];
        int kk=k>>3, kin=k&7, t4=kin&3, kh=kin>>2;
        int yt=y>>4, yin=y&15, g=yin&7, half=yin>>3;
        g_TYF[(((kk*16+yt)<<5) + ((g<<2)|t4))*4 + ((kh<<1)|half)] = f2tf32(v);
    } else if (t < 22528){                          // pw B-frags
        int u = t - 6144;
        int layer = u>>12; int v = u&4095;
        int k = v&63, o = v>>6;
        float w = pw_w[(layer*CH+o)*CH + k];
        int kk=k>>3, kin=k&7, t4=kin&3, kh=kin>>2;
        int ot=o>>3, g=o&7;
        g_PWF[layer*4096 + (((kk*8+ot)<<5)+((g<<2)|t4))*2 + kh] = f2tf32(w);
    } else if (t < 30720){                          // fc1 B-frags
        int u = t - 22528;
        int i = u&63, f = u>>6;
        float w = fc1w[f*CH + i];
        int kk=i>>3, kin=i&7, t4=kin&3, kh=kin>>2;
        int ot=f>>3, g=f&7;
        g_FC1F[(((kk*16+ot)<<5)+((g<<2)|t4))*2 + kh] = f2tf32(w);
    } else if (t < 36864){                          // forward-DFT (y) B-frags
        int u = t - 30720;
        int kk = u/192; int r = u%192;
        int nt = r/64;  int r2 = r%64;
        int lane = r2>>1, kh = r2&1;
        int t4 = lane&3, g = lane>>2;
        int y = kk*8 + t4 + 4*kh;
        int n = nt*8 + g;
        int k = n>>1;
        int rr = (k*y) & 255;
        double s,c; sincospi(2.0*rr/256.0, &s, &c);
        float v = (n&1)? (float)(-s) : (float)c;
        g_TYBF[((kk*3+nt)*32 + lane)*2 + kh] = f2tf32(v);
    } else if (t < 61440){                          // fwd x-DFT A-frags (M=48,K=512)
        int u = t - 36864;
        int slot = u&3, lane = (u>>2)&31, mt = (u>>7)%3, kk = u/384;
        int g = lane>>2, t4 = lane&3, half = slot&1, kh = slot>>1;
        int m = mt*16 + g + 8*half;
        int k = kk*8 + t4 + 4*kh;
        int j = m>>1, ri = m&1;
        int x = k>>1, xi = k&1;
        int keff = (j<12)? j : (j-24);
        int rr = ((keff*x)%256 + 256) & 255;
        double s,c; sincospi(2.0*rr/256.0, &s, &c);
        float v = (ri==0) ? ((xi==0)? (float)c : (float)s)
                          : ((xi==0)? (float)(-s) : (float)c);
        g_F1A[u] = f2tf32(v);
    } else if (t < 86016){                          // inv x-DFT B-frags (K=48,N=512)
        int u = t - 61440;
        int kh = u&1, lane = (u>>1)&31, nt = (u>>6)&63, kk = u>>12;
        int g = lane>>2, t4 = lane&3;
        int k = kk*8 + t4 + 4*kh;
        int j = k>>1, ri = k&1;
        int n = nt*8 + g;
        int x = n>>1, xi = n&1;
        int keff = (j<12)? j : (j-24);
        int rr = ((keff*x)%256 + 256) & 255;
        double s,c; sincospi(2.0*rr/256.0, &s, &c);
        float v = (ri==0) ? ((xi==0)? (float)c : (float)s)
                          : ((xi==0)? (float)(-s) : (float)c);
        g_F2B[u] = f2tf32(v * (1.0f/65536.0f));
    }
}

// ---------------- weight transpose for mix: [l][ky][j][i][o] ----------------
__global__ void k_wmix(const float* __restrict__ w1, const float* __restrict__ w2){
    int t = blockIdx.x*blockDim.x + threadIdx.x;
    if (t >= NLAYERS*CH*CH*MM*MM) return;
    int ky = t%12;
    int jm = (t/12)%12;
    int o  = (t/144)&63;
    int i  = (t/9216)&63;
    int layer = t/589824;
    float2 v1 = ((const float2*)w1)[t];
    float2 v2 = ((const float2*)w2)[t];
    float2* dst = (float2*)g_WMIX;
    size_t b0 = ((size_t)(layer*12+ky)*24);
    dst[(b0 + jm   )*4096 + i*64 + o] = v1;
    dst[(b0 + jm+12)*4096 + i*64 + o] = v2;
}

// ---------------- lift (fc0) -> Fy only (no global h write) ----------------
#define LIFT_SMEM (CH*PADH*4)
__global__ void __launch_bounds__(256) k_lift_fy(const float* __restrict__ x,
                                                 const float* __restrict__ fw,
                                                 const float* __restrict__ fb){
    extern __shared__ float HS[];   // [64][PADH]
    __shared__ float w[CH*3];
    __shared__ float bsh[CH];
    if (threadIdx.x < CH*3) w[threadIdx.x]   = fw[threadIdx.x];
    if (threadIdx.x < CH)   bsh[threadIdx.x] = fb[threadIdx.x];
    __syncthreads();
    int b = blockIdx.x>>8, xr = blockIdx.x&255;
    int y = threadIdx.x;
    float xin = x[(((size_t)b)<<16) + (xr<<8) + y];
    float gx = xr*(1.0f/255.0f), gy = y*(1.0f/255.0f);
    for (int wo=0; wo<CH; wo++){
        float v = w[wo*3]*xin + w[wo*3+1]*gx + w[wo*3+2]*gy + bsh[wo];
        HS[wo*PADH + y] = f2tf32(v);
    }
    __syncthreads();
    dft_epi(HS, b, xr, threadIdx.x>>5, threadIdx.x&31);
}

// ---------------- K-spec: fused (x-DFT -> mode mix -> x-inverse) per (b,ky) ----------------
#define BF1_F2 (64*8*32)                 /* 16384 float2 */
#define G_STRIDE 65
#define G_F (48*G_STRIDE)
#define AF2_F (6*4*32*4)
#define SPEC_SMEM ((BF1_F2*2 + G_F + AF2_F)*4)

__global__ void __launch_bounds__(512,1)
k_spec(int layer){
    extern __shared__ float sm[];
    float* BF1f = sm;
    float* Gs   = sm + 2*BF1_F2;
    float* AF2  = Gs + G_F;
    int b = blockIdx.x/12, ky = blockIdx.x%12;
    int tid = threadIdx.x, lane = tid&31, warp = tid>>5;

    const float2* fy = ((const float2*)g_Fy) + (((size_t)(b*MM+ky))<<14);
    for (int t=tid; t<64*256; t+=512){
        int c = t>>8, x = t&255;
        float2 v = fy[t];
        int nt=c>>3, g=c&7;
        int k0=2*x;
        int kk=k0>>3, t4=k0&3, kh=(k0>>2)&1;
        int base = ((kk*8+nt)<<5);
        BF1f[(base + ((g<<2)|t4    ))*2 + kh] = f2tf32(v.x);
        BF1f[(base + ((g<<2)|(t4+1)))*2 + kh] = f2tf32(v.y);
    }
    __syncthreads();

    {
        const float4* A4 = (const float4*)g_F1A;
        const float2* B2 = (const float2*)BF1f;
        for (int T=warp; T<24; T+=16){
            int mt = T%3, nt = T/3;
            float c0=0.f,c1=0.f,c2=0.f,c3=0.f;
#pragma unroll 8
            for (int kk=0; kk<64; kk++){
                float4 a = __ldg(A4 + ((kk*3+mt)<<5)+lane);
                float2 bf = B2[((kk*8+nt)<<5)+lane];
                mma_tf32(c0,c1,c2,c3, a.x,a.y,a.z,a.w, bf.x,bf.y);
            }
            int g=lane>>2, t4=lane&3;
            int row = mt*16+g, col = nt*8+2*t4;
            Gs[row*G_STRIDE+col]       = c0;
            Gs[row*G_STRIDE+col+1]     = c1;
            Gs[(row+8)*G_STRIDE+col]   = c2;
            Gs[(row+8)*G_STRIDE+col+1] = c3;
        }
    }
    __syncthreads();

    {
        const float2* WM = ((const float2*)g_WMIX) + ((size_t)((layer*12+ky)*24))*4096;
#pragma unroll
        for (int r=0; r<3; r++){
            int item = tid + 512*r;
            int j = item>>6, o = item&63;
            const float2* wrow = WM + j*4096 + o;
            const float* Gr = Gs + (2*j)*G_STRIDE;
            const float* Gi = Gs + (2*j+1)*G_STRIDE;
            float ar=0.f, ai=0.f;
#pragma unroll 8
            for (int i=0;i<64;i++){
                float2 wv = __ldg(wrow + i*64);
                float gr = Gr[i], gi = Gi[i];
                ar += gr*wv.x - gi*wv.y;
                ai += gr*wv.y + gi*wv.x;
            }
            int mt=o>>4, half=(o>>3)&1, gg=o&7;
            int k0=2*j;
            int kk=k0>>3, t40=k0&3, kh=(k0>>2)&1;
            int base = ((kk*4+mt)<<5);
            AF2[(base + ((gg<<2)|t40    ))*4 + ((kh<<1)|half)] = f2tf32(ar);
            AF2[(base + ((gg<<2)|(t40+1)))*4 + ((kh<<1)|half)] = f2tf32(ai);
        }
    }
    __syncthreads();

    {
        int mt = warp&3, ntb = (warp>>2)<<4;
        float4 Areg[6];
#pragma unroll
        for (int kk=0;kk<6;kk++)
            Areg[kk] = ((const float4*)AF2)[((kk*4+mt)<<5)+lane];
        int g=lane>>2, t4=lane&3;
        const float2* B2 = (const float2*)g_F2B;
        float2* E2 = (float2*)g_E;
        for (int ni=0;ni<16;ni++){
            int nt = ntb+ni;
            float c0=0.f,c1=0.f,c2=0.f,c3=0.f;
#pragma unroll
            for (int kk=0;kk<6;kk++){
                float2 bf = __ldg(B2 + ((kk*64+nt)<<5)+lane);
                mma_tf32(c0,c1,c2,c3, Areg[kk].x,Areg[kk].y,Areg[kk].z,Areg[kk].w,
                         bf.x,bf.y);
            }
            int x = nt*4+t4, o = mt*16+g;
            E2[((size_t)(b*HH+x)*CH + o  )*12 + ky] = make_float2(c0,c1);
            E2[((size_t)(b*HH+x)*CH + o+8)*12 + ky] = make_float2(c2,c3);
        }
    }
}

// ---------------- K5: fused layer; layer0 recomputes lift; layer3 fuses head ------------
// smem: AF 16640 (HS/head-AF overlay), EF 1536 (part overlay), bs 64, xs 256
#define K5_SMEM ((16640 + 1536 + 64 + 256)*4)

__global__ void __launch_bounds__(256,2)
k_layer(const float* __restrict__ xg, const float* __restrict__ fc0w,
        const float* __restrict__ fc0b, const float* __restrict__ pw_b,
        const float* __restrict__ fc1b, const float* __restrict__ fc2w,
        const float* __restrict__ fc2b, float* __restrict__ out, int layer){
    extern __shared__ float sm[];
    float* AF = sm;                  // h A-frags (16384) / HS overlay (16640) / head-AF
    float* HS = sm;
    float* EF = sm + 16640;          // E B-frags (1536) / head partials overlay
    float* bs = EF + 1536;
    float* xs = bs + 64;
    int b = blockIdx.x >> 8, xr = blockIdx.x & 255;
    int tid = threadIdx.x;

    if (layer == 0){
        // recompute lift: h0[i][y] = fc0(x, gx, gy)
        if (tid < 64)
            ((float4*)xs)[tid] = ((const float4*)(xg + (((size_t)b)<<16) + (xr<<8)))[tid];
        __syncthreads();
        float gx = xr*(1.0f/255.0f);
        for (int t=tid; t<CH*64; t+=256){
            int i=t>>6, q=t&63;
            float w0=__ldg(fc0w+i*3), w1=__ldg(fc0w+i*3+1), w2=__ldg(fc0w+i*3+2);
            float base = w1*gx + __ldg(fc0b+i);
            int kk=i>>3, kin=i&7, t4=kin&3, kh=kin>>2;
#pragma unroll
            for (int d=0; d<4; d++){
                int y = q*4+d;
                float v = w0*xs[y] + w2*(y*(1.0f/255.0f)) + base;
                int yt=y>>4, yin=y&15, g=yin&7, half=yin>>3;
                AF[(((kk*16+yt)<<5)+((g<<2)|t4))*4 + ((kh<<1)|half)] = f2tf32(v);
            }
        }
    } else {
        for (int t=tid; t<CH*64; t+=256){
            int i=t>>6, q=t&63;
            float4 v = ((const float4*)(g_h + (((size_t)(b*CH+i))<<16) + (xr<<8)))[q];
            int kk=i>>3, kin=i&7, t4=kin&3, kh=kin>>2;
            float vv[4] = {v.x, v.y, v.z, v.w};
#pragma unroll
            for (int d=0; d<4; d++){
                int y = q*4+d; int yt=y>>4, yin=y&15, g=yin&7, half=yin>>3;
                AF[(((kk*16+yt)<<5)+((g<<2)|t4))*4 + ((kh<<1)|half)] = f2tf32(vv[d]);
            }
        }
    }
    {   // E (coalesced) -> B-frags
        const float* Eb = g_E + ((size_t)(b*HH+xr))*CH*24;
        for (int t=tid; t<KXM*CH; t+=256){
            float v = Eb[t];
            int o = t/24, ke = t%24;
            int kk=ke>>3, t4=ke&3, kh=(ke>>2)&1;
            int ot=o>>3, g=o&7;
            EF[(((kk*8+ot)<<5)+((g<<2)|t4))*2 + kh] = f2tf32(v);
        }
    }
    if (tid<CH) bs[tid]=pw_b[layer*CH+tid];
    __syncthreads();

    int lane = tid & 31, warp = tid >> 5;
    int wy = warp >> 1, wo = warp & 1;        // 4 x 2 warp grid, 64y x 32o

    float c[4][4][4];
#pragma unroll
    for (int mi=0;mi<4;mi++)
#pragma unroll
        for (int ni=0;ni<4;ni++)
#pragma unroll
            for (int r=0;r<4;r++) c[mi][ni][r]=0.f;

    const float2* PW2 = ((const float2*)g_PWF) + layer*2048;
    for (int kk=0; kk<8; kk++){
        float2 bf[4];
#pragma unroll
        for (int ni=0;ni<4;ni++)
            bf[ni] = __ldg(PW2 + ((kk*8 + wo*4+ni)<<5)+lane);
#pragma unroll
        for (int mi=0;mi<4;mi++){
            float4 af = ((const float4*)AF)[((kk*16 + wy*4+mi)<<5)+lane];
#pragma unroll
            for (int ni=0;ni<4;ni++)
                mma_tf32(c[mi][ni][0],c[mi][ni][1],c[mi][ni][2],c[mi][ni][3],
                         af.x,af.y,af.z,af.w, bf[ni].x, bf[ni].y);
        }
    }
    const float4* TY4 = (const float4*)g_TYF;
    for (int kk=0; kk<3; kk++){
        float2 bf[4];
#pragma unroll
        for (int ni=0;ni<4;ni++)
            bf[ni] = ((const float2*)EF)[((kk*8 + wo*4+ni)<<5)+lane];
#pragma unroll
        for (int mi=0;mi<4;mi++){
            float4 af = __ldg(TY4 + ((kk*16 + wy*4+mi)<<5)+lane);
#pragma unroll
            for (int ni=0;ni<4;ni++)
                mma_tf32(c[mi][ni][0],c[mi][ni][1],c[mi][ni][2],c[mi][ni][3],
                         af.x,af.y,af.z,af.w, bf[ni].x, bf[ni].y);
        }
    }

    int g = lane>>2, t4 = lane&3;
    int dogelu = (layer < NLAYERS-1);
#pragma unroll
    for (int mi=0;mi<4;mi++){
#pragma unroll
        for (int ni=0;ni<4;ni++){
            int o = (wo*4+ni)*8 + 2*t4;
            float bb0 = bs[o], bb1 = bs[o+1];
            float v0 = c[mi][ni][0] + bb0;
            float v1 = c[mi][ni][1] + bb1;
            float v2 = c[mi][ni][2] + bb0;
            float v3 = c[mi][ni][3] + bb1;
            if (dogelu){ v0=gelu_f(v0); v1=gelu_f(v1); v2=gelu_f(v2); v3=gelu_f(v3); }
            c[mi][ni][0]=v0; c[mi][ni][1]=v1; c[mi][ni][2]=v2; c[mi][ni][3]=v3;
        }
    }

    if (layer < NLAYERS-1){
        // write h to global for next layer
#pragma unroll
        for (int mi=0;mi<4;mi++){
            int y = (wy*4+mi)*16 + g;
#pragma unroll
            for (int ni=0;ni<4;ni++){
                int o = (wo*4+ni)*8 + 2*t4;
                float* p0 = g_h + (((size_t)(b*CH+o  ))<<16) + (xr<<8);
                float* p1 = g_h + (((size_t)(b*CH+o+1))<<16) + (xr<<8);
                p0[y]   = c[mi][ni][0];
                p1[y]   = c[mi][ni][1];
                p0[y+8] = c[mi][ni][2];
                p1[y+8] = c[mi][ni][3];
            }
        }
        __syncthreads();
#pragma unroll
        for (int mi=0;mi<4;mi++){
            int y = (wy*4+mi)*16 + g;
#pragma unroll
            for (int ni=0;ni<4;ni++){
                int o = (wo*4+ni)*8 + 2*t4;
                HS[ o   *PADH + y  ] = f2tf32(c[mi][ni][0]);
                HS[(o+1)*PADH + y  ] = f2tf32(c[mi][ni][1]);
                HS[ o   *PADH + y+8] = f2tf32(c[mi][ni][2]);
                HS[(o+1)*PADH + y+8] = f2tf32(c[mi][ni][3]);
            }
        }
        __syncthreads();
        dft_epi(HS, b, xr, warp, lane);
        return;
    }

    // ---------------- layer 3: fused head ----------------
    __syncthreads();     // retire AF/EF reads
    // write h3 into AF as A-frags (k = channel o, m = y)
#pragma unroll
    for (int mi=0;mi<4;mi++){
#pragma unroll
        for (int ni=0;ni<4;ni++){
#pragma unroll
            for (int r=0;r<4;r++){
                int o = (wo*4+ni)*8 + 2*t4 + (r&1);
                int y = (wy*4+mi)*16 + g + ((r>>1)<<3);
                int kk=o>>3, kin=o&7, t4n=kin&3, khn=kin>>2;
                int yt=y>>4, yin=y&15, gn=yin&7, halfn=yin>>3;
                AF[(((kk*16+yt)<<5)+((gn<<2)|t4n))*4 + ((khn<<1)|halfn)] =
                    f2tf32(c[mi][ni][r]);
            }
        }
    }
    __syncthreads();

    float* part = EF;    // [2][256] overlay
    float s0[4] = {0.f,0.f,0.f,0.f}, s1[4] = {0.f,0.f,0.f,0.f};
    const float2* F2 = (const float2*)g_FC1F;
#pragma unroll
    for (int p=0; p<2; p++){
#pragma unroll
        for (int mi=0;mi<4;mi++)
#pragma unroll
            for (int ni=0;ni<4;ni++)
#pragma unroll
                for (int r=0;r<4;r++) c[mi][ni][r]=0.f;
        for (int kk=0; kk<8; kk++){
            float2 bf[4];
#pragma unroll
            for (int ni=0;ni<4;ni++)
                bf[ni] = __ldg(F2 + ((kk*16 + p*8 + wo*4+ni)<<5)+lane);
#pragma unroll
            for (int mi=0;mi<4;mi++){
                float4 af = ((const float4*)AF)[((kk*16 + wy*4+mi)<<5)+lane];
#pragma unroll
                for (int ni=0;ni<4;ni++)
                    mma_tf32(c[mi][ni][0],c[mi][ni][1],c[mi][ni][2],c[mi][ni][3],
                             af.x,af.y,af.z,af.w, bf[ni].x, bf[ni].y);
            }
        }
#pragma unroll
        for (int mi=0;mi<4;mi++){
#pragma unroll
            for (int ni=0;ni<4;ni++){
                int f = (p*8 + wo*4+ni)*8 + 2*t4;
                float ba = __ldg(fc1b+f), bb = __ldg(fc1b+f+1);
                float wa = __ldg(fc2w+f), wb = __ldg(fc2w+f+1);
                s0[mi] += gelu_f(c[mi][ni][0]+ba)*wa + gelu_f(c[mi][ni][1]+bb)*wb;
                s1[mi] += gelu_f(c[mi][ni][2]+ba)*wa + gelu_f(c[mi][ni][3]+bb)*wb;
            }
        }
    }
#pragma unroll
    for (int mi=0;mi<4;mi++){
        float a0 = s0[mi], a1 = s1[mi];
        a0 += __shfl_xor_sync(0xffffffffu, a0, 1);
        a0 += __shfl_xor_sync(0xffffffffu, a0, 2);
        a1 += __shfl_xor_sync(0xffffffffu, a1, 1);
        a1 += __shfl_xor_sync(0xffffffffu, a1, 2);
        if (t4==0){
            int y = (wy*4+mi)*16 + g;
            part[wo*WW + y]   = a0;
            part[wo*WW + y+8] = a1;
        }
    }
    __syncthreads();
    {
        int y = tid;
        float s = part[y] + part[WW+y] + __ldg(fc2b);
        out[(((size_t)b)<<16) + (xr<<8) + y] = s;
    }
}

// ---------------- launch ----------------
extern "C" void kernel_launch(void* const* d_in, const int* in_sizes, int n_in,
                              void* d_out, int out_size){
    (void)in_sizes; (void)n_in; (void)out_size;
    const float* x     = (const float*)d_in[0];
    const float* fc0_w = (const float*)d_in[1];
    const float* fc0_b = (const float*)d_in[2];
    const float* w1    = (const float*)d_in[3];
    const float* w2    = (const float*)d_in[4];
    const float* pw_w  = (const float*)d_in[5];
    const float* pw_b  = (const float*)d_in[6];
    const float* fc1_w = (const float*)d_in[7];
    const float* fc1_b = (const float*)d_in[8];
    const float* fc2_w = (const float*)d_in[9];
    const float* fc2_b = (const float*)d_in[10];
    float* out = (float*)d_out;

    cudaFuncSetAttribute(k_layer,   cudaFuncAttributeMaxDynamicSharedMemorySize, K5_SMEM);
    cudaFuncSetAttribute(k_spec,    cudaFuncAttributeMaxDynamicSharedMemorySize, SPEC_SMEM);
    cudaFuncSetAttribute(k_lift_fy, cudaFuncAttributeMaxDynamicSharedMemorySize, LIFT_SMEM);

    k_tables<<<24,256>>>();
    k_frw<<<336,256>>>(pw_w, fc1_w);
    k_wmix<<<9216,256>>>(w1, w2);
    k_lift_fy<<<BATCH*HH,256,LIFT_SMEM>>>(x, fc0_w, fc0_b);
    for (int l=0; l<NLAYERS; l++){
        k_spec<<<BATCH*MM,512,SPEC_SMEM>>>(l);
        k_layer<<<BATCH*HH,256,K5_SMEM>>>(x, fc0_w, fc0_b, pw_b,
                                          fc1_b, fc2_w, fc2_b, out, l);
    }
}